// round 2
// baseline (speedup 1.0000x reference)
#include <cuda_runtime.h>
#include <math.h>

#define NEG_SLOPE 0.1f
#define RES_SCALE 0.70710678118654752440f
#define DEMOD_EPS 1e-5f

// ---------------------------------------------------------------------------
// Scratch (static device globals; allocation inside kernel_launch is banned)
// ---------------------------------------------------------------------------
__device__ float g_y1[8 * 256 * 64 * 64];   // block1 output, 33.5 MB
__device__ float g_wT1[256 * 9 * 256];      // conv1 weights transposed [ci][k][oc]
__device__ float g_wT2[256 * 9 * 128];      // conv2 weights transposed
__device__ float g_s1[8 * 256];
__device__ float g_n1[8 * 256];
__device__ float g_s2[8 * 256];
__device__ float g_n2[8 * 128];
__device__ float g_d1[8 * 256];
__device__ float g_d2[8 * 128];

// ---------------------------------------------------------------------------
// Bilinear 2x upsample sample (half-pixel, matches jax.image.resize 'bilinear'
// including edge renormalization).  (yy,xx) are coords in the 2x grid.
// out[2k]   = 0.25*in[k-1] + 0.75*in[k]   (clamped)
// out[2k+1] = 0.75*in[k]   + 0.25*in[k+1] (clamped)
// ---------------------------------------------------------------------------
__device__ __forceinline__ float bilin_up(const float* __restrict__ plane,
                                          int yy, int xx, int Hin, int Win) {
    int ky = yy >> 1, kx = xx >> 1;
    int ylo, yhi, xlo, xhi;
    float wy, wx;  // weight of (ylo, xlo)
    if (yy & 1) { ylo = ky; yhi = (ky + 1 < Hin) ? ky + 1 : Hin - 1; wy = 0.75f; }
    else        { ylo = (ky - 1 > 0) ? ky - 1 : 0; yhi = ky;         wy = 0.25f; }
    if (xx & 1) { xlo = kx; xhi = (kx + 1 < Win) ? kx + 1 : Win - 1; wx = 0.75f; }
    else        { xlo = (kx - 1 > 0) ? kx - 1 : 0; xhi = kx;         wx = 0.25f; }
    float v00 = plane[ylo * Win + xlo];
    float v01 = plane[ylo * Win + xhi];
    float v10 = plane[yhi * Win + xlo];
    float v11 = plane[yhi * Win + xhi];
    float top = wx * v00 + (1.f - wx) * v01;
    float bot = wx * v10 + (1.f - wx) * v11;
    return wy * top + (1.f - wy) * bot;
}

// ---------------------------------------------------------------------------
// Affine: out[b,o] = dot(vec[b,:512], W[o,:512]) + bias[o]; one warp per (b,o)
// ---------------------------------------------------------------------------
__global__ void __launch_bounds__(256) affine_kernel(
    const float* __restrict__ vec, const float* __restrict__ Wm,
    const float* __restrict__ bias, float* __restrict__ out, int OUT) {
    int gw = (blockIdx.x * blockDim.x + threadIdx.x) >> 5;
    int lane = threadIdx.x & 31;
    if (gw >= 8 * OUT) return;
    int b = gw / OUT, o = gw - b * OUT;
    const float* v = vec + b * 512;
    const float* wr = Wm + (size_t)o * 512;
    float s = 0.f;
#pragma unroll 4
    for (int i = lane; i < 512; i += 32) s = fmaf(v[i], wr[i], s);
#pragma unroll
    for (int off = 16; off; off >>= 1) s += __shfl_xor_sync(0xffffffffu, s, off);
    if (lane == 0) out[b * OUT + o] = s + bias[o];
}

// ---------------------------------------------------------------------------
// demod[b,o] = rsqrt( sum_i (sum_k w[o,i,k]^2) * styles[b,i]^2 + eps )
// one block per o, 256 threads, 8 batches accumulated in registers
// ---------------------------------------------------------------------------
__global__ void __launch_bounds__(256) demod_kernel(
    const float* __restrict__ convw, const float* __restrict__ styles,
    float* __restrict__ demod, int CIN, int COUT) {
    int o = blockIdx.x;
    int tid = threadIdx.x;
    float part[8];
#pragma unroll
    for (int b = 0; b < 8; b++) part[b] = 0.f;
    for (int i = tid; i < CIN; i += 256) {
        const float* wp = convw + ((size_t)o * CIN + i) * 9;
        float wsq = 0.f;
#pragma unroll
        for (int k = 0; k < 9; k++) { float t = wp[k]; wsq = fmaf(t, t, wsq); }
#pragma unroll
        for (int b = 0; b < 8; b++) {
            float s = styles[b * CIN + i];
            part[b] = fmaf(wsq, s * s, part[b]);
        }
    }
    __shared__ float sm[8][9];
#pragma unroll
    for (int b = 0; b < 8; b++)
#pragma unroll
        for (int off = 16; off; off >>= 1)
            part[b] += __shfl_xor_sync(0xffffffffu, part[b], off);
    int warp = tid >> 5, lane = tid & 31;
    if (lane == 0)
        for (int b = 0; b < 8; b++) sm[warp][b] = part[b];
    __syncthreads();
    if (tid < 8) {
        float t = 0.f;
        for (int w2 = 0; w2 < 8; w2++) t += sm[w2][tid];
        demod[tid * COUT + o] = rsqrtf(t + DEMOD_EPS);
    }
}

// ---------------------------------------------------------------------------
// Weight transpose: wT[(ci*9+k)*COUT + oc] = w[oc][ci][k]
// ---------------------------------------------------------------------------
__global__ void transpose_w(const float* __restrict__ w, float* __restrict__ wT,
                            int CIN, int COUT) {
    int idx = blockIdx.x * blockDim.x + threadIdx.x;
    int total = CIN * 9 * COUT;
    if (idx >= total) return;
    int oc = idx % COUT;
    int rem = idx / COUT;
    int k = rem % 9;
    int ci = rem / 9;
    wT[idx] = w[((size_t)oc * CIN + ci) * 9 + k];
}

// ---------------------------------------------------------------------------
// Fused modulated 3x3 conv (+ optional on-the-fly bilinear 2x upsample of the
// input) + demod + noise + LeakyReLU(0.1).
// Block tile: 64 output channels x (4 rows x 16 cols) pixels. 256 threads,
// each computes a 4(oc) x 4(pix) register microtile. K chunked by 8 channels.
// ---------------------------------------------------------------------------
template <int CIN, int COUT, int H, int W, bool UP>
__global__ void __launch_bounds__(256) conv3x3_kernel(
    const float* __restrict__ in, const float* __restrict__ wT,
    const float* __restrict__ styles, const float* __restrict__ demod,
    const float* __restrict__ noise, float* __restrict__ out) {
    constexpr int KC = 8;
    constexpr int Hin = UP ? H / 2 : H;
    constexpr int Win = UP ? W / 2 : W;

    __shared__ float s_in[KC][6][21];   // 18 used per row; 21 stride kills conflicts
    __shared__ float s_w[KC][9][64];

    const int tid = threadIdx.x;
    const int x0 = blockIdx.x * 16;
    const int y0 = blockIdx.y * 4;
    const int bz = blockIdx.z;
    const int b = bz / (COUT / 64);
    const int ocb = (bz % (COUT / 64)) * 64;

    const int ty = tid >> 4;         // 0..15 : oc quad
    const int tx = tid & 15;         // 0..15 : pixel quad
    const int r_t = tx >> 2;         // row 0..3
    const int c4 = (tx & 3) * 4;     // col base 0/4/8/12

    float acc[4][4];
#pragma unroll
    for (int i = 0; i < 4; i++)
#pragma unroll
        for (int j = 0; j < 4; j++) acc[i][j] = 0.f;

    for (int c0 = 0; c0 < CIN; c0 += KC) {
        // ---- load input tile (style-scaled, zero-padded, optionally upsampled)
        for (int idx = tid; idx < KC * 6 * 18; idx += 256) {
            int ci = idx / 108;
            int rem = idx - ci * 108;
            int rr = rem / 18;
            int cc = rem - rr * 18;
            int yy = y0 - 1 + rr;
            int xx = x0 - 1 + cc;
            float v = 0.f;
            if (yy >= 0 && yy < H && xx >= 0 && xx < W) {
                const float* plane =
                    in + (size_t)(b * CIN + c0 + ci) * (Hin * Win);
                if (UP) v = bilin_up(plane, yy, xx, Hin, Win);
                else    v = plane[yy * Win + xx];
                v *= styles[b * CIN + c0 + ci];
            }
            s_in[ci][rr][cc] = v;
        }
        // ---- load weight slab (coalesced from pre-transposed layout)
#pragma unroll
        for (int l = 0; l < (KC * 9 * 64) / 256; l++) {
            int idx = tid + l * 256;
            int ci = idx / 576;
            int rem = idx - ci * 576;
            (&s_w[0][0][0])[ci * 576 + rem] =
                wT[(size_t)(c0 + ci) * 9 * COUT + (rem >> 6) * COUT + ocb + (rem & 63)];
        }
        __syncthreads();

#pragma unroll 2
        for (int ci = 0; ci < KC; ci++) {
#pragma unroll
            for (int ky = 0; ky < 3; ky++) {
                float iv[6];
#pragma unroll
                for (int j = 0; j < 6; j++) iv[j] = s_in[ci][r_t + ky][c4 + j];
#pragma unroll
                for (int kx = 0; kx < 3; kx++) {
                    float wv[4];
#pragma unroll
                    for (int oo = 0; oo < 4; oo++)
                        wv[oo] = s_w[ci][ky * 3 + kx][ty * 4 + oo];
#pragma unroll
                    for (int oo = 0; oo < 4; oo++)
#pragma unroll
                        for (int pp = 0; pp < 4; pp++)
                            acc[oo][pp] = fmaf(wv[oo], iv[kx + pp], acc[oo][pp]);
                }
            }
        }
        __syncthreads();
    }

    const int y = y0 + r_t;
#pragma unroll
    for (int oo = 0; oo < 4; oo++) {
        int oc = ocb + ty * 4 + oo;
        float d = demod[b * COUT + oc];
        float nz = noise[b * COUT + oc];
        float* orow = out + ((size_t)(b * COUT + oc) * H + y) * W + x0 + c4;
#pragma unroll
        for (int pp = 0; pp < 4; pp++) {
            float v = fmaf(acc[oo][pp], d, nz);
            orow[pp] = (v >= 0.f) ? v : NEG_SLOPE * v;
        }
    }
}

// ---------------------------------------------------------------------------
// toRGB: rgb_out = (xout . rgb_w + rgb_b + upsample2x(rgb_in)) * sqrt(0.5)
// one thread per (b, y, x); computes all 3 output channels
// ---------------------------------------------------------------------------
__global__ void __launch_bounds__(256) rgb_kernel(
    const float* __restrict__ xout, const float* __restrict__ rgb_in,
    const float* __restrict__ rgb_w, const float* __restrict__ rgb_b,
    float* __restrict__ rgb_out) {
    __shared__ float sw[384];
    for (int i = threadIdx.x; i < 384; i += 256) sw[i] = rgb_w[i];
    __syncthreads();
    int idx = blockIdx.x * 256 + threadIdx.x;
    if (idx >= 8 * 128 * 128) return;
    int b = idx >> 14;
    int p = idx & 16383;
    int y = p >> 7, x = p & 127;
    const float* xp = xout + (size_t)b * 128 * 16384 + p;
    float a0 = 0.f, a1 = 0.f, a2 = 0.f;
#pragma unroll 4
    for (int o = 0; o < 128; o++) {
        float v = xp[(size_t)o * 16384];
        a0 = fmaf(v, sw[o], a0);
        a1 = fmaf(v, sw[128 + o], a1);
        a2 = fmaf(v, sw[256 + o], a2);
    }
    float a[3] = {a0, a1, a2};
#pragma unroll
    for (int c = 0; c < 3; c++) {
        const float* plane = rgb_in + ((size_t)b * 3 + c) * 64 * 64;
        float up = bilin_up(plane, y, x, 64, 64);
        rgb_out[((size_t)(b * 3 + c) * 128 + y) * 128 + x] =
            (a[c] + rgb_b[c] + up) * RES_SCALE;
    }
}

// ---------------------------------------------------------------------------
// Launcher
// ---------------------------------------------------------------------------
extern "C" void kernel_launch(void* const* d_in, const int* in_sizes, int n_in,
                              void* d_out, int out_size) {
    const float* x       = (const float*)d_in[0];   // [8,256,64,64]
    const float* w       = (const float*)d_in[1];   // [8,512]
    const float* n       = (const float*)d_in[2];   // [8,512]
    const float* rgb     = (const float*)d_in[3];   // [8,3,64,64]
    const float* conv1_w = (const float*)d_in[4];   // [256,256,3,3]
    const float* A1_w    = (const float*)d_in[5];   // [256,512]
    const float* A1_b    = (const float*)d_in[6];   // [256]
    const float* B1_w    = (const float*)d_in[7];   // [256,512]
    const float* B1_b    = (const float*)d_in[8];   // [256]
    const float* conv2_w = (const float*)d_in[9];   // [128,256,3,3]
    const float* A2_w    = (const float*)d_in[10];  // [256,512]
    const float* A2_b    = (const float*)d_in[11];  // [256]
    const float* B2_w    = (const float*)d_in[12];  // [128,512]
    const float* B2_b    = (const float*)d_in[13];  // [128]
    const float* rgb_w   = (const float*)d_in[14];  // [3,128,1,1]
    const float* rgb_b   = (const float*)d_in[15];  // [3]

    static float *p_y1 = nullptr, *p_wT1, *p_wT2, *p_s1, *p_n1, *p_s2, *p_n2,
                 *p_d1, *p_d2;
    if (!p_y1) {
        cudaGetSymbolAddress((void**)&p_y1, g_y1);
        cudaGetSymbolAddress((void**)&p_wT1, g_wT1);
        cudaGetSymbolAddress((void**)&p_wT2, g_wT2);
        cudaGetSymbolAddress((void**)&p_s1, g_s1);
        cudaGetSymbolAddress((void**)&p_n1, g_n1);
        cudaGetSymbolAddress((void**)&p_s2, g_s2);
        cudaGetSymbolAddress((void**)&p_n2, g_n2);
        cudaGetSymbolAddress((void**)&p_d1, g_d1);
        cudaGetSymbolAddress((void**)&p_d2, g_d2);
    }

    float* xout = (float*)d_out;                          // [8,128,128,128]
    float* rgbout = xout + (size_t)8 * 128 * 128 * 128;   // [8,3,128,128]

    // styles / noise affines
    affine_kernel<<<256, 256>>>(w, A1_w, A1_b, p_s1, 256);
    affine_kernel<<<256, 256>>>(n, B1_w, B1_b, p_n1, 256);
    affine_kernel<<<256, 256>>>(w, A2_w, A2_b, p_s2, 256);
    affine_kernel<<<128, 256>>>(n, B2_w, B2_b, p_n2, 128);

    // demodulation factors
    demod_kernel<<<256, 256>>>(conv1_w, p_s1, p_d1, 256, 256);
    demod_kernel<<<128, 256>>>(conv2_w, p_s2, p_d2, 256, 128);

    // weight transposes (coalesced conv loads)
    transpose_w<<<(256 * 9 * 256 + 255) / 256, 256>>>(conv1_w, p_wT1, 256, 256);
    transpose_w<<<(256 * 9 * 128 + 255) / 256, 256>>>(conv2_w, p_wT2, 256, 128);

    // block 1: mod-conv 256->256 @64x64 (+demod+noise+lrelu) -> y1
    conv3x3_kernel<256, 256, 64, 64, false>
        <<<dim3(4, 16, 8 * 4), 256>>>(x, p_wT1, p_s1, p_d1, p_n1, p_y1);

    // block 2: upsample(fused) + mod-conv 256->128 @128x128 -> xout
    conv3x3_kernel<256, 128, 128, 128, true>
        <<<dim3(8, 32, 8 * 2), 256>>>(p_y1, p_wT2, p_s2, p_d2, p_n2, xout);

    // toRGB + residual rgb upsample
    rgb_kernel<<<512, 256>>>(xout, rgb, rgb_w, rgb_b, rgbout);
}

// round 4
// speedup vs baseline: 2.9078x; 2.9078x over previous
#include <cuda_runtime.h>
#include <cuda_bf16.h>
#include <math.h>
#include <stdint.h>

#define NEG_SLOPE 0.1f
#define RES_SCALE 0.70710678118654752440f
#define DEMOD_EPS 1e-5f

// ---------------- scratch globals (no allocation allowed) -------------------
__device__ __align__(16) float g_y1[8 * 64 * 64 * 256];              // conv1 out NHWC
__device__ __align__(16) __nv_bfloat16 g_p1H[8 * 66 * 66 * 256];     // styled pad in1
__device__ __align__(16) __nv_bfloat16 g_p1L[8 * 66 * 66 * 256];
__device__ __align__(16) __nv_bfloat16 g_p2H[8 * 130 * 130 * 256];   // styled up in2
__device__ __align__(16) __nv_bfloat16 g_p2L[8 * 130 * 130 * 256];
__device__ __align__(16) __nv_bfloat16 g_wH1[2 * 36 * 8192];         // pre-swizzled B img
__device__ __align__(16) __nv_bfloat16 g_wL1[2 * 36 * 8192];
__device__ __align__(16) __nv_bfloat16 g_wH2[1 * 36 * 8192];
__device__ __align__(16) __nv_bfloat16 g_wL2[1 * 36 * 8192];
__device__ float g_s1[8 * 256], g_n1[8 * 256], g_s2[8 * 256], g_n2[8 * 128];
__device__ float g_d1[8 * 256], g_d2[8 * 128];

// ---------------- portable PTX helpers (sm_80-level, compile on sm_103) -----
__device__ __forceinline__ uint32_t smem_u32(const void* p) {
    uint32_t a;
    asm("{ .reg .u64 t; cvta.to.shared.u64 t, %1; cvt.u32.u64 %0, t; }" : "=r"(a) : "l"(p));
    return a;
}
#define CPA16(dst, src) \
    asm volatile("cp.async.cg.shared.global [%0], [%1], 16;" :: "r"(dst), "l"(src))
#define CPA_COMMIT() asm volatile("cp.async.commit_group;" ::: "memory")
#define LDSM4(r, addr) \
    asm volatile("ldmatrix.sync.aligned.m8n8.x4.shared.b16 {%0,%1,%2,%3}, [%4];" \
                 : "=r"((r)[0]), "=r"((r)[1]), "=r"((r)[2]), "=r"((r)[3]) : "r"(addr))
#define MMA16816(c, a, b) \
    asm volatile("mma.sync.aligned.m16n8k16.row.col.f32.bf16.bf16.f32 " \
                 "{%0,%1,%2,%3},{%4,%5,%6,%7},{%8,%9},{%0,%1,%2,%3};" \
                 : "+f"((c)[0]), "+f"((c)[1]), "+f"((c)[2]), "+f"((c)[3]) \
                 : "r"((a)[0]), "r"((a)[1]), "r"((a)[2]), "r"((a)[3]), \
                   "r"((b)[0]), "r"((b)[1]))

__device__ __forceinline__ void bsplit(float v, __nv_bfloat16& h, __nv_bfloat16& l) {
    h = __float2bfloat16_rn(v);
    l = __float2bfloat16_rn(v - __bfloat162float(h));
}

// ---------------- prep kernels ----------------------------------------------
__global__ void __launch_bounds__(256) affine_kernel(
    const float* __restrict__ vec, const float* __restrict__ Wm,
    const float* __restrict__ bias, float* __restrict__ out, int OUT) {
    int gw = (blockIdx.x * blockDim.x + threadIdx.x) >> 5, lane = threadIdx.x & 31;
    if (gw >= 8 * OUT) return;
    int b = gw / OUT, o = gw - b * OUT;
    const float* v = vec + b * 512;
    const float* wr = Wm + (size_t)o * 512;
    float s = 0.f;
#pragma unroll 4
    for (int i = lane; i < 512; i += 32) s = fmaf(v[i], wr[i], s);
#pragma unroll
    for (int off = 16; off; off >>= 1) s += __shfl_xor_sync(0xffffffffu, s, off);
    if (lane == 0) out[b * OUT + o] = s + bias[o];
}

__global__ void __launch_bounds__(256) demod_kernel(
    const float* __restrict__ convw, const float* __restrict__ styles,
    float* __restrict__ demod, int CIN, int COUT) {
    int o = blockIdx.x, tid = threadIdx.x;
    float part[8];
#pragma unroll
    for (int b = 0; b < 8; b++) part[b] = 0.f;
    for (int i = tid; i < CIN; i += 256) {
        const float* wp = convw + ((size_t)o * CIN + i) * 9;
        float wsq = 0.f;
#pragma unroll
        for (int k = 0; k < 9; k++) { float t = wp[k]; wsq = fmaf(t, t, wsq); }
#pragma unroll
        for (int b = 0; b < 8; b++) {
            float s = styles[b * CIN + i];
            part[b] = fmaf(wsq, s * s, part[b]);
        }
    }
    __shared__ float sm[8][9];
#pragma unroll
    for (int b = 0; b < 8; b++)
#pragma unroll
        for (int off = 16; off; off >>= 1)
            part[b] += __shfl_xor_sync(0xffffffffu, part[b], off);
    int warp = tid >> 5, lane = tid & 31;
    if (lane == 0)
        for (int b = 0; b < 8; b++) sm[warp][b] = part[b];
    __syncthreads();
    if (tid < 8) {
        float t = 0.f;
        for (int w2 = 0; w2 < 8; w2++) t += sm[w2][tid];
        demod[tid * COUT + o] = rsqrtf(t + DEMOD_EPS);
    }
}

// weights -> pre-swizzled n-major slice images.
// slice s = tap*4 + cb; element (n, k) at bf16 index:
//   n*64 + (((k>>3) ^ (n&7))<<3) + (k&7)      [XOR-swizzled 16B chunks]
__global__ void __launch_bounds__(256) prep_wimg(
    const float* __restrict__ w, __nv_bfloat16* __restrict__ BH,
    __nv_bfloat16* __restrict__ BL, int OCB) {
    int idx = blockIdx.x * 256 + threadIdx.x;
    if (idx >= OCB * 36 * 8192) return;
    int k = idx & 63, n = (idx >> 6) & 127, s = (idx >> 13) % 36, ob = idx / (36 * 8192);
    int tap = s >> 2, cb = s & 3;
    float v = w[((size_t)(ob * 128 + n) * 256 + cb * 64 + k) * 9 + tap];
    uint32_t off = n * 64 + (((k >> 3) ^ (n & 7)) << 3) + (k & 7);
    size_t base = ((size_t)ob * 36 + s) * 8192;
    __nv_bfloat16 h, l; bsplit(v, h, l);
    BH[base + off] = h; BL[base + off] = l;
}

__global__ void zero_border(__nv_bfloat16* H, __nv_bfloat16* L, int Hp) {
    int per = 2 * Hp + 2 * (Hp - 2);
    int p = blockIdx.x, c = threadIdx.x;
    int b = p / per, r = p % per;
    int y, x;
    if (r < Hp) { y = 0; x = r; }
    else if (r < 2 * Hp) { y = Hp - 1; x = r - Hp; }
    else { int q = r - 2 * Hp; y = 1 + (q >> 1); x = (q & 1) ? Hp - 1 : 0; }
    size_t o = (((size_t)b * Hp + y) * Hp + x) * 256 + c;
    H[o] = __float2bfloat16_rn(0.f); L[o] = __float2bfloat16_rn(0.f);
}

__global__ void __launch_bounds__(256) prep_pad1(
    const float* __restrict__ x, const float* __restrict__ s,
    __nv_bfloat16* __restrict__ H, __nv_bfloat16* __restrict__ L) {
    int b = blockIdx.y, y = blockIdx.x, c = threadIdx.x;
    float sc = s[b * 256 + c];
    const float* row = x + ((size_t)(b * 256 + c) * 64 + y) * 64;
    size_t dst = (((size_t)b * 66 + y + 1) * 66 + 1) * 256 + c;
    for (int xx = 0; xx < 64; xx++) {
        __nv_bfloat16 h, l; bsplit(row[xx] * sc, h, l);
        H[dst + (size_t)xx * 256] = h; L[dst + (size_t)xx * 256] = l;
    }
}

__global__ void __launch_bounds__(256) prep_pad2(
    const float* __restrict__ y1, const float* __restrict__ s,
    __nv_bfloat16* __restrict__ H, __nv_bfloat16* __restrict__ L) {
    int b = blockIdx.y, yy = blockIdx.x, c = threadIdx.x;
    float sc = s[b * 256 + c];
    int ky = yy >> 1, ylo, yhi; float wy;
    if (yy & 1) { ylo = ky; yhi = (ky + 1 < 64) ? ky + 1 : 63; wy = 0.75f; }
    else        { ylo = (ky > 0) ? ky - 1 : 0; yhi = ky;       wy = 0.25f; }
    const float* base = y1 + (size_t)b * 64 * 64 * 256;
    size_t dst = (((size_t)b * 130 + yy + 1) * 130 + 1) * 256 + c;
    for (int xx = 0; xx < 128; xx++) {
        int kx = xx >> 1, xlo, xhi; float wx;
        if (xx & 1) { xlo = kx; xhi = (kx + 1 < 64) ? kx + 1 : 63; wx = 0.75f; }
        else        { xlo = (kx > 0) ? kx - 1 : 0; xhi = kx;       wx = 0.25f; }
        float v00 = base[((size_t)ylo * 64 + xlo) * 256 + c];
        float v01 = base[((size_t)ylo * 64 + xhi) * 256 + c];
        float v10 = base[((size_t)yhi * 64 + xlo) * 256 + c];
        float v11 = base[((size_t)yhi * 64 + xhi) * 256 + c];
        float v = (wy * (wx * v00 + (1.f - wx) * v01) +
                   (1.f - wy) * (wx * v10 + (1.f - wx) * v11)) * sc;
        __nv_bfloat16 h, l; bsplit(v, h, l);
        H[dst + (size_t)xx * 256] = h; L[dst + (size_t)xx * 256] = l;
    }
}

// ---------------- mma.sync implicit-GEMM conv --------------------------------
// Block: 128 px x 128 oc. 8 warps: warp (wid>>2) -> 64-px half, (wid&3) -> 32-oc.
// K = 36 slices of 64 (tap-major). Split-bf16 3-term. 2-stage cp.async pipeline.
// smem buf (per stage 64KB): Ah[128][64] Al Bh[128n][64k] Bl, all XOR-swizzled.
template <int W, int Hp, int COUT, bool NCHW>
__global__ void __launch_bounds__(256, 1) conv_mma(
    const __nv_bfloat16* __restrict__ AH, const __nv_bfloat16* __restrict__ AL,
    const __nv_bfloat16* __restrict__ BH, const __nv_bfloat16* __restrict__ BL,
    const float* __restrict__ demod, const float* __restrict__ noise,
    float* __restrict__ out) {
    extern __shared__ char smem[];
    constexpr int LOGW = (W == 64) ? 6 : 7;
    const int tid = threadIdx.x, wid = tid >> 5, lane = tid & 31;
    const int ocb = blockIdx.y, b = blockIdx.z;
    const int y0 = blockIdx.x * (128 / W);
    const uint32_t sbase = smem_u32(smem);

    const int wm = (wid >> 2) * 64;   // warp pixel-row offset
    const int wn = (wid & 3) * 32;    // warp oc offset

    // per-lane ldmatrix address components
    const uint32_t a_lane = (((lane >> 3) & 1) << 10) + ((lane & 7) << 7);
    const int a_csel = lane >> 4;
    const uint32_t b_lane = (((lane >> 4) & 1) << 10) + ((lane & 7) << 7);
    const int b_csel = (lane >> 3) & 1;
    const int swz = lane & 7;

    float c[4][4][4];
#pragma unroll
    for (int i = 0; i < 4; i++)
#pragma unroll
        for (int j = 0; j < 4; j++)
#pragma unroll
            for (int v = 0; v < 4; v++) c[i][j][v] = 0.f;

    const size_t bimg = (size_t)ocb * 36 * 8192;

    // slice loader (cp.async): A 2x16KB + B 2x16KB into stage buf
    auto load_slice = [&](int s, int buf) {
        const int tap = s >> 2, cb = s & 3;
        const int dy = tap / 3 - 1, dx = tap % 3 - 1, ci0 = cb * 64;
        const uint32_t base = sbase + buf * 65536;
#pragma unroll
        for (int l = 0; l < 4; l++) {
            int i = tid + l * 256;          // 0..1023
            int r = i >> 3, q = i & 7;
            int gy = y0 + (r >> LOGW) + dy + 1;
            int gx = (r & (W - 1)) + dx + 1;
            size_t src = (((size_t)b * Hp + gy) * Hp + gx) * 256 + ci0 + q * 8;
            uint32_t dst = base + r * 128 + ((q ^ (r & 7)) << 4);
            CPA16(dst, AH + src);
            CPA16(dst + 16384, AL + src);
        }
        const char* bh = (const char*)(BH + bimg + (size_t)s * 8192);
        const char* bl = (const char*)(BL + bimg + (size_t)s * 8192);
#pragma unroll
        for (int l = 0; l < 4; l++) {
            int i = tid + l * 256;
            CPA16(base + 32768 + i * 16, bh + i * 16);
            CPA16(base + 49152 + i * 16, bl + i * 16);
        }
        CPA_COMMIT();
    };

    load_slice(0, 0);
    for (int s = 0; s < 36; s++) {
        const int buf = s & 1;
        if (s < 35) {
            load_slice(s + 1, buf ^ 1);
            asm volatile("cp.async.wait_group 1;" ::: "memory");
        } else {
            asm volatile("cp.async.wait_group 0;" ::: "memory");
        }
        __syncthreads();

        const uint32_t aw = sbase + buf * 65536 + wm * 128;
        const uint32_t bw = sbase + buf * 65536 + 32768 + wn * 128;
#pragma unroll
        for (int ks = 0; ks < 4; ks++) {
            uint32_t Ah[4][4], Al[4][4], Bh[2][4], Bl[2][4];
#pragma unroll
            for (int mt = 0; mt < 4; mt++) {
                uint32_t ad = aw + mt * 2048 + a_lane + (((ks * 2 + a_csel) ^ swz) << 4);
                LDSM4(Ah[mt], ad);
                LDSM4(Al[mt], ad + 16384);
            }
#pragma unroll
            for (int q = 0; q < 2; q++) {
                uint32_t bd = bw + q * 2048 + b_lane + (((ks * 2 + b_csel) ^ swz) << 4);
                LDSM4(Bh[q], bd);
                LDSM4(Bl[q], bd + 16384);
            }
#pragma unroll
            for (int mt = 0; mt < 4; mt++)
#pragma unroll
                for (int nt = 0; nt < 4; nt++)
                    MMA16816(c[mt][nt], Ah[mt], (&Bh[nt >> 1][(nt & 1) * 2]));
#pragma unroll
            for (int mt = 0; mt < 4; mt++)
#pragma unroll
                for (int nt = 0; nt < 4; nt++)
                    MMA16816(c[mt][nt], Ah[mt], (&Bl[nt >> 1][(nt & 1) * 2]));
#pragma unroll
            for (int mt = 0; mt < 4; mt++)
#pragma unroll
                for (int nt = 0; nt < 4; nt++)
                    MMA16816(c[mt][nt], Al[mt], (&Bh[nt >> 1][(nt & 1) * 2]));
        }
        __syncthreads();
    }

    // ---- epilogue: stage through smem (pipeline bufs dead now) --------------
    float* s_out = (float*)smem;                 // [128 oc][132 px]
    float* sd = s_out + 128 * 132;               // demod[128]
    float* sn = sd + 128;                        // noise[128]
    const int g = lane >> 2, tg = lane & 3;
#pragma unroll
    for (int mt = 0; mt < 4; mt++)
#pragma unroll
        for (int nt = 0; nt < 4; nt++)
#pragma unroll
            for (int v = 0; v < 4; v++) {
                int p = wm + mt * 16 + g + ((v >> 1) << 3);
                int n = wn + nt * 8 + tg * 2 + (v & 1);
                s_out[n * 132 + p] = c[mt][nt][v];
            }
    if (tid < 128) {
        sd[tid] = demod[b * COUT + ocb * 128 + tid];
        sn[tid] = noise[b * COUT + ocb * 128 + tid];
    }
    __syncthreads();

    if (NCHW) {
        // conv2: out [b][oc][y0][x], W=128, one y-row per block
        int oc = tid >> 1, xh = tid & 1;
        float d = sd[oc], nz = sn[oc];
        float4* dst = (float4*)(out + (((size_t)(b * COUT + oc) * W + y0) * W + xh * 64));
        const float4* srcv = (const float4*)(s_out + oc * 132 + xh * 64);
#pragma unroll
        for (int j4 = 0; j4 < 16; j4++) {
            float4 v = srcv[j4];
            float r0 = fmaf(v.x, d, nz); r0 = (r0 >= 0.f) ? r0 : NEG_SLOPE * r0;
            float r1 = fmaf(v.y, d, nz); r1 = (r1 >= 0.f) ? r1 : NEG_SLOPE * r1;
            float r2 = fmaf(v.z, d, nz); r2 = (r2 >= 0.f) ? r2 : NEG_SLOPE * r2;
            float r3 = fmaf(v.w, d, nz); r3 = (r3 >= 0.f) ? r3 : NEG_SLOPE * r3;
            dst[j4] = make_float4(r0, r1, r2, r3);
        }
    } else {
        // conv1: out NHWC [b][y][x][256], W=64, two y-rows per block
        int p = tid >> 1, half = tid & 1;
        int y = y0 + (p >> 6), x = p & 63;
        float* dst = out + (((size_t)(b * 64 + y) * 64 + x) * 256) + ocb * 128 + half * 64;
#pragma unroll
        for (int j = 0; j < 64; j += 4) {
            float vv[4];
#pragma unroll
            for (int e = 0; e < 4; e++) {
                int oc = half * 64 + j + e;
                float v = fmaf(s_out[oc * 132 + p], sd[oc], sn[oc]);
                vv[e] = (v >= 0.f) ? v : NEG_SLOPE * v;
            }
            *(float4*)(dst + j) = make_float4(vv[0], vv[1], vv[2], vv[3]);
        }
    }
}

// ---------------- toRGB ------------------------------------------------------
__device__ __forceinline__ float bilin_up64(const float* __restrict__ plane,
                                            int yy, int xx) {
    int ky = yy >> 1, kx = xx >> 1, ylo, yhi, xlo, xhi;
    float wy, wx;
    if (yy & 1) { ylo = ky; yhi = (ky + 1 < 64) ? ky + 1 : 63; wy = 0.75f; }
    else        { ylo = (ky > 0) ? ky - 1 : 0; yhi = ky;       wy = 0.25f; }
    if (xx & 1) { xlo = kx; xhi = (kx + 1 < 64) ? kx + 1 : 63; wx = 0.75f; }
    else        { xlo = (kx > 0) ? kx - 1 : 0; xhi = kx;       wx = 0.25f; }
    float v00 = plane[ylo * 64 + xlo], v01 = plane[ylo * 64 + xhi];
    float v10 = plane[yhi * 64 + xlo], v11 = plane[yhi * 64 + xhi];
    return wy * (wx * v00 + (1.f - wx) * v01) + (1.f - wy) * (wx * v10 + (1.f - wx) * v11);
}

__global__ void __launch_bounds__(256) rgb_kernel(
    const float* __restrict__ xout, const float* __restrict__ rgb_in,
    const float* __restrict__ rgb_w, const float* __restrict__ rgb_b,
    float* __restrict__ rgb_out) {
    __shared__ float sw[384];
    for (int i = threadIdx.x; i < 384; i += 256) sw[i] = rgb_w[i];
    __syncthreads();
    int idx = blockIdx.x * 256 + threadIdx.x;
    if (idx >= 8 * 128 * 128) return;
    int b = idx >> 14, p = idx & 16383, y = p >> 7, x = p & 127;
    const float* xp = xout + (size_t)b * 128 * 16384 + p;
    float a0 = 0.f, a1 = 0.f, a2 = 0.f;
#pragma unroll 4
    for (int o = 0; o < 128; o++) {
        float v = xp[(size_t)o * 16384];
        a0 = fmaf(v, sw[o], a0); a1 = fmaf(v, sw[128 + o], a1); a2 = fmaf(v, sw[256 + o], a2);
    }
    float a[3] = {a0, a1, a2};
#pragma unroll
    for (int c = 0; c < 3; c++) {
        const float* plane = rgb_in + ((size_t)b * 3 + c) * 4096;
        rgb_out[((size_t)(b * 3 + c) * 128 + y) * 128 + x] =
            (a[c] + rgb_b[c] + bilin_up64(plane, y, x)) * RES_SCALE;
    }
}

// ---------------- launcher ---------------------------------------------------
extern "C" void kernel_launch(void* const* d_in, const int* in_sizes, int n_in,
                              void* d_out, int out_size) {
    const float* x       = (const float*)d_in[0];
    const float* w       = (const float*)d_in[1];
    const float* n       = (const float*)d_in[2];
    const float* rgb     = (const float*)d_in[3];
    const float* conv1_w = (const float*)d_in[4];
    const float* A1_w    = (const float*)d_in[5];
    const float* A1_b    = (const float*)d_in[6];
    const float* B1_w    = (const float*)d_in[7];
    const float* B1_b    = (const float*)d_in[8];
    const float* conv2_w = (const float*)d_in[9];
    const float* A2_w    = (const float*)d_in[10];
    const float* A2_b    = (const float*)d_in[11];
    const float* B2_w    = (const float*)d_in[12];
    const float* B2_b    = (const float*)d_in[13];
    const float* rgb_w   = (const float*)d_in[14];
    const float* rgb_b   = (const float*)d_in[15];

    static float* p_y1 = nullptr;
    static __nv_bfloat16 *p1H, *p1L, *p2H, *p2L, *wH1, *wL1, *wH2, *wL2;
    static float *p_s1, *p_n1, *p_s2, *p_n2, *p_d1, *p_d2;
    if (!p_y1) {
        cudaGetSymbolAddress((void**)&p_y1, g_y1);
        cudaGetSymbolAddress((void**)&p1H, g_p1H);
        cudaGetSymbolAddress((void**)&p1L, g_p1L);
        cudaGetSymbolAddress((void**)&p2H, g_p2H);
        cudaGetSymbolAddress((void**)&p2L, g_p2L);
        cudaGetSymbolAddress((void**)&wH1, g_wH1);
        cudaGetSymbolAddress((void**)&wL1, g_wL1);
        cudaGetSymbolAddress((void**)&wH2, g_wH2);
        cudaGetSymbolAddress((void**)&wL2, g_wL2);
        cudaGetSymbolAddress((void**)&p_s1, g_s1);
        cudaGetSymbolAddress((void**)&p_n1, g_n1);
        cudaGetSymbolAddress((void**)&p_s2, g_s2);
        cudaGetSymbolAddress((void**)&p_n2, g_n2);
        cudaGetSymbolAddress((void**)&p_d1, g_d1);
        cudaGetSymbolAddress((void**)&p_d2, g_d2);
        cudaFuncSetAttribute(conv_mma<64, 66, 256, false>,
                             cudaFuncAttributeMaxDynamicSharedMemorySize, 131072);
        cudaFuncSetAttribute(conv_mma<128, 130, 128, true>,
                             cudaFuncAttributeMaxDynamicSharedMemorySize, 131072);
    }

    float* xout = (float*)d_out;                         // [8,128,128,128]
    float* rgbout = xout + (size_t)8 * 128 * 128 * 128;  // [8,3,128,128]

    affine_kernel<<<256, 256>>>(w, A1_w, A1_b, p_s1, 256);
    affine_kernel<<<256, 256>>>(n, B1_w, B1_b, p_n1, 256);
    affine_kernel<<<256, 256>>>(w, A2_w, A2_b, p_s2, 256);
    affine_kernel<<<128, 256>>>(n, B2_w, B2_b, p_n2, 128);
    demod_kernel<<<256, 256>>>(conv1_w, p_s1, p_d1, 256, 256);
    demod_kernel<<<128, 256>>>(conv2_w, p_s2, p_d2, 256, 128);
    prep_wimg<<<(2 * 36 * 8192 + 255) / 256, 256>>>(conv1_w, wH1, wL1, 2);
    prep_wimg<<<(1 * 36 * 8192 + 255) / 256, 256>>>(conv2_w, wH2, wL2, 1);
    zero_border<<<8 * (2 * 66 + 2 * 64), 256>>>(p1H, p1L, 66);
    zero_border<<<8 * (2 * 130 + 2 * 128), 256>>>(p2H, p2L, 130);
    prep_pad1<<<dim3(64, 8), 256>>>(x, p_s1, p1H, p1L);

    conv_mma<64, 66, 256, false><<<dim3(32, 2, 8), 256, 131072>>>(
        p1H, p1L, wH1, wL1, p_d1, p_n1, p_y1);

    prep_pad2<<<dim3(128, 8), 256>>>(p_y1, p_s2, p2H, p2L);

    conv_mma<128, 130, 128, true><<<dim3(128, 1, 8), 256, 131072>>>(
        p2H, p2L, wH2, wL2, p_d2, p_n2, xout);

    rgb_kernel<<<512, 256>>>(xout, rgb, rgb_w, rgb_b, rgbout);
}

// round 5
// speedup vs baseline: 4.2705x; 1.4686x over previous
#include <cuda_runtime.h>
#include <cuda_fp16.h>
#include <math.h>
#include <stdint.h>

#define NEG_SLOPE 0.1f
#define RES_SCALE 0.70710678118654752440f
#define DEMOD_EPS 1e-5f

// ---------------- scratch globals (no allocation allowed) -------------------
__device__ __align__(16) float g_y1[8 * 64 * 64 * 256];        // conv1 out NHWC
__device__ __align__(16) __half g_p1H[8 * 66 * 66 * 256];      // styled pad in1 hi
__device__ __align__(16) __half g_p1L[8 * 66 * 66 * 256];      // styled pad in1 lo
__device__ __align__(16) __half g_p2H[8 * 130 * 130 * 256];    // styled up in2 hi
__device__ __align__(16) __half g_p2L[8 * 130 * 130 * 256];    // styled up in2 lo
__device__ __align__(16) __half g_wH1[2 * 36 * 8192];          // pre-swizzled B img
__device__ __align__(16) __half g_wH2[1 * 36 * 8192];
__device__ float g_s1[8 * 256], g_n1[8 * 256], g_s2[8 * 256], g_n2[8 * 128];
__device__ float g_d1[8 * 256], g_d2[8 * 128];

// ---------------- portable PTX helpers ---------------------------------------
__device__ __forceinline__ uint32_t smem_u32(const void* p) {
    uint32_t a;
    asm("{ .reg .u64 t; cvta.to.shared.u64 t, %1; cvt.u32.u64 %0, t; }" : "=r"(a) : "l"(p));
    return a;
}
#define CPA16(dst, src) \
    asm volatile("cp.async.cg.shared.global [%0], [%1], 16;" :: "r"(dst), "l"(src))
#define CPA_COMMIT() asm volatile("cp.async.commit_group;" ::: "memory")
#define LDSM4(r, addr) \
    asm volatile("ldmatrix.sync.aligned.m8n8.x4.shared.b16 {%0,%1,%2,%3}, [%4];" \
                 : "=r"((r)[0]), "=r"((r)[1]), "=r"((r)[2]), "=r"((r)[3]) : "r"(addr))
#define MMA16816(c, a, b) \
    asm volatile("mma.sync.aligned.m16n8k16.row.col.f32.f16.f16.f32 " \
                 "{%0,%1,%2,%3},{%4,%5,%6,%7},{%8,%9},{%0,%1,%2,%3};" \
                 : "+f"((c)[0]), "+f"((c)[1]), "+f"((c)[2]), "+f"((c)[3]) \
                 : "r"((a)[0]), "r"((a)[1]), "r"((a)[2]), "r"((a)[3]), \
                   "r"((b)[0]), "r"((b)[1]))

__device__ __forceinline__ void hsplit(float v, __half& h, __half& l) {
    h = __float2half_rn(v);
    l = __float2half_rn(v - __half2float(h));
}

// ---------------- prep kernels ----------------------------------------------
__global__ void __launch_bounds__(256) affine_kernel(
    const float* __restrict__ vec, const float* __restrict__ Wm,
    const float* __restrict__ bias, float* __restrict__ out, int OUT) {
    int gw = (blockIdx.x * blockDim.x + threadIdx.x) >> 5, lane = threadIdx.x & 31;
    if (gw >= 8 * OUT) return;
    int b = gw / OUT, o = gw - b * OUT;
    const float* v = vec + b * 512;
    const float* wr = Wm + (size_t)o * 512;
    float s = 0.f;
#pragma unroll 4
    for (int i = lane; i < 512; i += 32) s = fmaf(v[i], wr[i], s);
#pragma unroll
    for (int off = 16; off; off >>= 1) s += __shfl_xor_sync(0xffffffffu, s, off);
    if (lane == 0) out[b * OUT + o] = s + bias[o];
}

__global__ void __launch_bounds__(256) demod_kernel(
    const float* __restrict__ convw, const float* __restrict__ styles,
    float* __restrict__ demod, int CIN, int COUT) {
    int o = blockIdx.x, tid = threadIdx.x;
    float part[8];
#pragma unroll
    for (int b = 0; b < 8; b++) part[b] = 0.f;
    for (int i = tid; i < CIN; i += 256) {
        const float* wp = convw + ((size_t)o * CIN + i) * 9;
        float wsq = 0.f;
#pragma unroll
        for (int k = 0; k < 9; k++) { float t = wp[k]; wsq = fmaf(t, t, wsq); }
#pragma unroll
        for (int b = 0; b < 8; b++) {
            float s = styles[b * CIN + i];
            part[b] = fmaf(wsq, s * s, part[b]);
        }
    }
    __shared__ float sm[8][9];
#pragma unroll
    for (int b = 0; b < 8; b++)
#pragma unroll
        for (int off = 16; off; off >>= 1)
            part[b] += __shfl_xor_sync(0xffffffffu, part[b], off);
    int warp = tid >> 5, lane = tid & 31;
    if (lane == 0)
        for (int b = 0; b < 8; b++) sm[warp][b] = part[b];
    __syncthreads();
    if (tid < 8) {
        float t = 0.f;
        for (int w2 = 0; w2 < 8; w2++) t += sm[w2][tid];
        demod[tid * COUT + o] = rsqrtf(t + DEMOD_EPS);
    }
}

// weights -> pre-swizzled n-major slice images (single fp16).
__global__ void __launch_bounds__(256) prep_wimg(
    const float* __restrict__ w, __half* __restrict__ BH, int OCB) {
    int idx = blockIdx.x * 256 + threadIdx.x;
    if (idx >= OCB * 36 * 8192) return;
    int k = idx & 63, n = (idx >> 6) & 127, s = (idx >> 13) % 36, ob = idx / (36 * 8192);
    int tap = s >> 2, cb = s & 3;
    float v = w[((size_t)(ob * 128 + n) * 256 + cb * 64 + k) * 9 + tap];
    uint32_t off = n * 64 + (((k >> 3) ^ (n & 7)) << 3) + (k & 7);
    BH[((size_t)ob * 36 + s) * 8192 + off] = __float2half_rn(v);
}

__global__ void zero_border(__half* H, __half* L, int Hp) {
    int per = 2 * Hp + 2 * (Hp - 2);
    int p = blockIdx.x, c = threadIdx.x;
    int b = p / per, r = p % per;
    int y, x;
    if (r < Hp) { y = 0; x = r; }
    else if (r < 2 * Hp) { y = Hp - 1; x = r - Hp; }
    else { int q = r - 2 * Hp; y = 1 + (q >> 1); x = (q & 1) ? Hp - 1 : 0; }
    size_t o = (((size_t)b * Hp + y) * Hp + x) * 256 + c;
    H[o] = __float2half_rn(0.f); L[o] = __float2half_rn(0.f);
}

__global__ void __launch_bounds__(256) prep_pad1(
    const float* __restrict__ x, const float* __restrict__ s,
    __half* __restrict__ H, __half* __restrict__ L) {
    int b = blockIdx.y, y = blockIdx.x, c = threadIdx.x;
    float sc = s[b * 256 + c];
    const float* row = x + ((size_t)(b * 256 + c) * 64 + y) * 64;
    size_t dst = (((size_t)b * 66 + y + 1) * 66 + 1) * 256 + c;
    for (int xx = 0; xx < 64; xx++) {
        __half h, l; hsplit(row[xx] * sc, h, l);
        H[dst + (size_t)xx * 256] = h; L[dst + (size_t)xx * 256] = l;
    }
}

__global__ void __launch_bounds__(256) prep_pad2(
    const float* __restrict__ y1, const float* __restrict__ s,
    __half* __restrict__ H, __half* __restrict__ L) {
    int b = blockIdx.y, yy = blockIdx.x, c = threadIdx.x;
    float sc = s[b * 256 + c];
    int ky = yy >> 1, ylo, yhi; float wy;
    if (yy & 1) { ylo = ky; yhi = (ky + 1 < 64) ? ky + 1 : 63; wy = 0.75f; }
    else        { ylo = (ky > 0) ? ky - 1 : 0; yhi = ky;       wy = 0.25f; }
    const float* base = y1 + (size_t)b * 64 * 64 * 256;
    size_t dst = (((size_t)b * 130 + yy + 1) * 130 + 1) * 256 + c;
    for (int xx = 0; xx < 128; xx++) {
        int kx = xx >> 1, xlo, xhi; float wx;
        if (xx & 1) { xlo = kx; xhi = (kx + 1 < 64) ? kx + 1 : 63; wx = 0.75f; }
        else        { xlo = (kx > 0) ? kx - 1 : 0; xhi = kx;       wx = 0.25f; }
        float v00 = base[((size_t)ylo * 64 + xlo) * 256 + c];
        float v01 = base[((size_t)ylo * 64 + xhi) * 256 + c];
        float v10 = base[((size_t)yhi * 64 + xlo) * 256 + c];
        float v11 = base[((size_t)yhi * 64 + xhi) * 256 + c];
        float v = (wy * (wx * v00 + (1.f - wx) * v01) +
                   (1.f - wy) * (wx * v10 + (1.f - wx) * v11)) * sc;
        __half h, l; hsplit(v, h, l);
        H[dst + (size_t)xx * 256] = h; L[dst + (size_t)xx * 256] = l;
    }
}

// ---------------- mma.sync implicit-GEMM conv --------------------------------
// 128 px x 128 oc per CTA. A split fp16 hi/lo, B single fp16: D = AhBh + AlBh.
// K = 36 slices of 64. 2-stage cp.async pipeline, 48KB/stage.
// conv2 (NCHW) additionally fuses the toRGB epilogue.
template <int W, int Hp, int COUT, bool NCHW>
__global__ void __launch_bounds__(256, 2) conv_mma(
    const __half* __restrict__ AH, const __half* __restrict__ AL,
    const __half* __restrict__ BHg,
    const float* __restrict__ demod, const float* __restrict__ noise,
    float* __restrict__ out,
    const float* __restrict__ rgb_in, const float* __restrict__ rgb_w,
    const float* __restrict__ rgb_b, float* __restrict__ rgb_out) {
    extern __shared__ char smem[];
    constexpr int LOGW = (W == 64) ? 6 : 7;
    constexpr uint32_t STG = 49152;
    const int tid = threadIdx.x, wid = tid >> 5, lane = tid & 31;
    const int ocb = blockIdx.y, b = blockIdx.z;
    const int y0 = blockIdx.x * (128 / W);
    const uint32_t sbase = smem_u32(smem);

    const int wm = (wid >> 2) * 64;
    const int wn = (wid & 3) * 32;

    const uint32_t a_lane = (((lane >> 3) & 1) << 10) + ((lane & 7) << 7);
    const int a_csel = lane >> 4;
    const uint32_t b_lane = (((lane >> 4) & 1) << 10) + ((lane & 7) << 7);
    const int b_csel = (lane >> 3) & 1;
    const int swz = lane & 7;

    float c[4][4][4];
#pragma unroll
    for (int i = 0; i < 4; i++)
#pragma unroll
        for (int j = 0; j < 4; j++)
#pragma unroll
            for (int v = 0; v < 4; v++) c[i][j][v] = 0.f;

    const size_t bimg = (size_t)ocb * 36 * 8192;

    auto load_slice = [&](int s, int buf) {
        const int tap = s >> 2, cb = s & 3;
        const int dy = tap / 3 - 1, dx = tap % 3 - 1, ci0 = cb * 64;
        const uint32_t base = sbase + buf * STG;
#pragma unroll
        for (int l = 0; l < 4; l++) {
            int i = tid + l * 256;
            int r = i >> 3, q = i & 7;
            int gy = y0 + (r >> LOGW) + dy + 1;
            int gx = (r & (W - 1)) + dx + 1;
            size_t src = (((size_t)b * Hp + gy) * Hp + gx) * 256 + ci0 + q * 8;
            uint32_t dst = base + r * 128 + ((q ^ (r & 7)) << 4);
            CPA16(dst, AH + src);
            CPA16(dst + 16384, AL + src);
        }
        const char* bh = (const char*)(BHg + bimg + (size_t)s * 8192);
#pragma unroll
        for (int l = 0; l < 4; l++) {
            int i = tid + l * 256;
            CPA16(base + 32768 + i * 16, bh + i * 16);
        }
        CPA_COMMIT();
    };

    load_slice(0, 0);
    for (int s = 0; s < 36; s++) {
        const int buf = s & 1;
        if (s < 35) {
            load_slice(s + 1, buf ^ 1);
            asm volatile("cp.async.wait_group 1;" ::: "memory");
        } else {
            asm volatile("cp.async.wait_group 0;" ::: "memory");
        }
        __syncthreads();

        const uint32_t aw = sbase + buf * STG + wm * 128;
        const uint32_t bw = sbase + buf * STG + 32768 + wn * 128;
#pragma unroll
        for (int ks = 0; ks < 4; ks++) {
            uint32_t Ah[4][4], Al[4][4], Bh[2][4];
#pragma unroll
            for (int mt = 0; mt < 4; mt++) {
                uint32_t ad = aw + mt * 2048 + a_lane + (((ks * 2 + a_csel) ^ swz) << 4);
                LDSM4(Ah[mt], ad);
                LDSM4(Al[mt], ad + 16384);
            }
#pragma unroll
            for (int q = 0; q < 2; q++) {
                uint32_t bd = bw + q * 2048 + b_lane + (((ks * 2 + b_csel) ^ swz) << 4);
                LDSM4(Bh[q], bd);
            }
#pragma unroll
            for (int mt = 0; mt < 4; mt++)
#pragma unroll
                for (int nt = 0; nt < 4; nt++)
                    MMA16816(c[mt][nt], Ah[mt], (&Bh[nt >> 1][(nt & 1) * 2]));
#pragma unroll
            for (int mt = 0; mt < 4; mt++)
#pragma unroll
                for (int nt = 0; nt < 4; nt++)
                    MMA16816(c[mt][nt], Al[mt], (&Bh[nt >> 1][(nt & 1) * 2]));
        }
        __syncthreads();
    }

    // ---- epilogue: stage through smem ---------------------------------------
    float* s_out = (float*)smem;                 // [128 oc][132 px]
    float* sd = s_out + 128 * 132;
    float* sn = sd + 128;
    float* sw = sn + 128;                        // rgb weights [384]
    const int g = lane >> 2, tg = lane & 3;
#pragma unroll
    for (int mt = 0; mt < 4; mt++)
#pragma unroll
        for (int nt = 0; nt < 4; nt++)
#pragma unroll
            for (int v = 0; v < 4; v++) {
                int p = wm + mt * 16 + g + ((v >> 1) << 3);
                int n = wn + nt * 8 + tg * 2 + (v & 1);
                s_out[n * 132 + p] = c[mt][nt][v];
            }
    if (tid < 128) {
        sd[tid] = demod[b * COUT + ocb * 128 + tid];
        sn[tid] = noise[b * COUT + ocb * 128 + tid];
    }
    if (NCHW)
        for (int i = tid; i < 384; i += 256) sw[i] = rgb_w[i];
    __syncthreads();

    if (NCHW) {
        // conv2: out [b][oc][y0][x], W=128, one y-row per block; fused toRGB
        int oc = tid >> 1, xh = tid & 1;
        float d = sd[oc], nz = sn[oc];
        float4* dst = (float4*)(out + (((size_t)(b * COUT + oc) * W + y0) * W + xh * 64));
        float4* srow = (float4*)(s_out + oc * 132 + xh * 64);
#pragma unroll
        for (int j4 = 0; j4 < 16; j4++) {
            float4 v = srow[j4];
            float r0 = fmaf(v.x, d, nz); r0 = (r0 >= 0.f) ? r0 : NEG_SLOPE * r0;
            float r1 = fmaf(v.y, d, nz); r1 = (r1 >= 0.f) ? r1 : NEG_SLOPE * r1;
            float r2 = fmaf(v.z, d, nz); r2 = (r2 >= 0.f) ? r2 : NEG_SLOPE * r2;
            float r3 = fmaf(v.w, d, nz); r3 = (r3 >= 0.f) ? r3 : NEG_SLOPE * r3;
            float4 rv = make_float4(r0, r1, r2, r3);
            dst[j4] = rv;
            srow[j4] = rv;   // keep activated values for rgb stage
        }
        __syncthreads();
        if (tid < 128) {
            int x = tid;
            float a0 = 0.f, a1 = 0.f, a2 = 0.f;
#pragma unroll 4
            for (int o = 0; o < 128; o++) {
                float v = s_out[o * 132 + x];
                a0 = fmaf(v, sw[o], a0);
                a1 = fmaf(v, sw[128 + o], a1);
                a2 = fmaf(v, sw[256 + o], a2);
            }
            float a[3] = {a0, a1, a2};
            // bilinear 2x upsample of rgb_in at (y0, x)
            int ky = y0 >> 1, kx = x >> 1, ylo, yhi, xlo, xhi;
            float wy, wx;
            if (y0 & 1) { ylo = ky; yhi = (ky + 1 < 64) ? ky + 1 : 63; wy = 0.75f; }
            else        { ylo = (ky > 0) ? ky - 1 : 0; yhi = ky;       wy = 0.25f; }
            if (x & 1)  { xlo = kx; xhi = (kx + 1 < 64) ? kx + 1 : 63; wx = 0.75f; }
            else        { xlo = (kx > 0) ? kx - 1 : 0; xhi = kx;       wx = 0.25f; }
#pragma unroll
            for (int ch = 0; ch < 3; ch++) {
                const float* plane = rgb_in + ((size_t)b * 3 + ch) * 4096;
                float v00 = plane[ylo * 64 + xlo], v01 = plane[ylo * 64 + xhi];
                float v10 = plane[yhi * 64 + xlo], v11 = plane[yhi * 64 + xhi];
                float up = wy * (wx * v00 + (1.f - wx) * v01) +
                           (1.f - wy) * (wx * v10 + (1.f - wx) * v11);
                rgb_out[((size_t)(b * 3 + ch) * 128 + y0) * 128 + x] =
                    (a[ch] + rgb_b[ch] + up) * RES_SCALE;
            }
        }
    } else {
        // conv1: out NHWC [b][y][x][256], W=64, two y-rows per block
        int p = tid >> 1, half = tid & 1;
        int y = y0 + (p >> 6), x = p & 63;
        float* dst = out + (((size_t)(b * 64 + y) * 64 + x) * 256) + ocb * 128 + half * 64;
#pragma unroll
        for (int j = 0; j < 64; j += 4) {
            float vv[4];
#pragma unroll
            for (int e = 0; e < 4; e++) {
                int oc = half * 64 + j + e;
                float v = fmaf(s_out[oc * 132 + p], sd[oc], sn[oc]);
                vv[e] = (v >= 0.f) ? v : NEG_SLOPE * v;
            }
            *(float4*)(dst + j) = make_float4(vv[0], vv[1], vv[2], vv[3]);
        }
    }
}

// ---------------- launcher ---------------------------------------------------
extern "C" void kernel_launch(void* const* d_in, const int* in_sizes, int n_in,
                              void* d_out, int out_size) {
    const float* x       = (const float*)d_in[0];
    const float* w       = (const float*)d_in[1];
    const float* n       = (const float*)d_in[2];
    const float* rgb     = (const float*)d_in[3];
    const float* conv1_w = (const float*)d_in[4];
    const float* A1_w    = (const float*)d_in[5];
    const float* A1_b    = (const float*)d_in[6];
    const float* B1_w    = (const float*)d_in[7];
    const float* B1_b    = (const float*)d_in[8];
    const float* conv2_w = (const float*)d_in[9];
    const float* A2_w    = (const float*)d_in[10];
    const float* A2_b    = (const float*)d_in[11];
    const float* B2_w    = (const float*)d_in[12];
    const float* B2_b    = (const float*)d_in[13];
    const float* rgb_w   = (const float*)d_in[14];
    const float* rgb_b   = (const float*)d_in[15];

    static float* p_y1 = nullptr;
    static __half *p1H, *p1L, *p2H, *p2L, *wH1, *wH2;
    static float *p_s1, *p_n1, *p_s2, *p_n2, *p_d1, *p_d2;
    if (!p_y1) {
        cudaGetSymbolAddress((void**)&p_y1, g_y1);
        cudaGetSymbolAddress((void**)&p1H, g_p1H);
        cudaGetSymbolAddress((void**)&p1L, g_p1L);
        cudaGetSymbolAddress((void**)&p2H, g_p2H);
        cudaGetSymbolAddress((void**)&p2L, g_p2L);
        cudaGetSymbolAddress((void**)&wH1, g_wH1);
        cudaGetSymbolAddress((void**)&wH2, g_wH2);
        cudaGetSymbolAddress((void**)&p_s1, g_s1);
        cudaGetSymbolAddress((void**)&p_n1, g_n1);
        cudaGetSymbolAddress((void**)&p_s2, g_s2);
        cudaGetSymbolAddress((void**)&p_n2, g_n2);
        cudaGetSymbolAddress((void**)&p_d1, g_d1);
        cudaGetSymbolAddress((void**)&p_d2, g_d2);
        cudaFuncSetAttribute(conv_mma<64, 66, 256, false>,
                             cudaFuncAttributeMaxDynamicSharedMemorySize, 98304);
        cudaFuncSetAttribute(conv_mma<128, 130, 128, true>,
                             cudaFuncAttributeMaxDynamicSharedMemorySize, 98304);
    }

    float* xout = (float*)d_out;                         // [8,128,128,128]
    float* rgbout = xout + (size_t)8 * 128 * 128 * 128;  // [8,3,128,128]

    affine_kernel<<<256, 256>>>(w, A1_w, A1_b, p_s1, 256);
    affine_kernel<<<256, 256>>>(n, B1_w, B1_b, p_n1, 256);
    affine_kernel<<<256, 256>>>(w, A2_w, A2_b, p_s2, 256);
    affine_kernel<<<128, 256>>>(n, B2_w, B2_b, p_n2, 128);
    demod_kernel<<<256, 256>>>(conv1_w, p_s1, p_d1, 256, 256);
    demod_kernel<<<128, 256>>>(conv2_w, p_s2, p_d2, 256, 128);
    prep_wimg<<<(2 * 36 * 8192 + 255) / 256, 256>>>(conv1_w, wH1, 2);
    prep_wimg<<<(1 * 36 * 8192 + 255) / 256, 256>>>(conv2_w, wH2, 1);
    zero_border<<<8 * (2 * 66 + 2 * 64), 256>>>(p1H, p1L, 66);
    zero_border<<<8 * (2 * 130 + 2 * 128), 256>>>(p2H, p2L, 130);
    prep_pad1<<<dim3(64, 8), 256>>>(x, p_s1, p1H, p1L);

    conv_mma<64, 66, 256, false><<<dim3(32, 2, 8), 256, 98304>>>(
        p1H, p1L, wH1, p_d1, p_n1, p_y1, nullptr, nullptr, nullptr, nullptr);

    prep_pad2<<<dim3(128, 8), 256>>>(p_y1, p_s2, p2H, p2L);

    conv_mma<128, 130, 128, true><<<dim3(128, 1, 8), 256, 98304>>>(
        p2H, p2L, wH2, p_d2, p_n2, xout, rgb, rgb_w, rgb_b, rgbout);
}

// round 7
// speedup vs baseline: 6.5344x; 1.5301x over previous
#include <cuda_runtime.h>
#include <cuda_fp16.h>
#include <math.h>
#include <stdint.h>

#define NEG_SLOPE 0.1f
#define RES_SCALE 0.70710678118654752440f
#define DEMOD_EPS 1e-5f

// ---------------- scratch globals (no allocation allowed) -------------------
__device__ __align__(16) float g_y1[8 * 64 * 64 * 256];        // conv1 out NHWC
__device__ __align__(16) __half g_p1H[8 * 66 * 66 * 256];      // styled pad in1
__device__ __align__(16) __half g_p2H[8 * 130 * 130 * 256];    // styled up in2
__device__ __align__(16) __half g_wH1[2 * 36 * 8192];          // pre-swizzled B img
__device__ __align__(16) __half g_wH2[1 * 36 * 8192];
__device__ float g_s1[8 * 256], g_n1[8 * 256], g_s2[8 * 256], g_n2[8 * 128];
__device__ float g_d1[8 * 256], g_d2[8 * 128];

// ---------------- portable PTX helpers ---------------------------------------
__device__ __forceinline__ uint32_t smem_u32(const void* p) {
    uint32_t a;
    asm("{ .reg .u64 t; cvta.to.shared.u64 t, %1; cvt.u32.u64 %0, t; }" : "=r"(a) : "l"(p));
    return a;
}
#define CPA16(dst, src) \
    asm volatile("cp.async.cg.shared.global [%0], [%1], 16;" :: "r"(dst), "l"(src))
#define CPA_COMMIT() asm volatile("cp.async.commit_group;" ::: "memory")
#define LDSM4(r, addr) \
    asm volatile("ldmatrix.sync.aligned.m8n8.x4.shared.b16 {%0,%1,%2,%3}, [%4];" \
                 : "=r"((r)[0]), "=r"((r)[1]), "=r"((r)[2]), "=r"((r)[3]) : "r"(addr))
#define MMA16816(c, a, b) \
    asm volatile("mma.sync.aligned.m16n8k16.row.col.f32.f16.f16.f32 " \
                 "{%0,%1,%2,%3},{%4,%5,%6,%7},{%8,%9},{%0,%1,%2,%3};" \
                 : "+f"((c)[0]), "+f"((c)[1]), "+f"((c)[2]), "+f"((c)[3]) \
                 : "r"((a)[0]), "r"((a)[1]), "r"((a)[2]), "r"((a)[3]), \
                   "r"((b)[0]), "r"((b)[1]))

// ---------------- prep kernels ----------------------------------------------
__global__ void __launch_bounds__(256) affine_kernel(
    const float* __restrict__ vec, const float* __restrict__ Wm,
    const float* __restrict__ bias, float* __restrict__ out, int OUT) {
    int gw = (blockIdx.x * blockDim.x + threadIdx.x) >> 5, lane = threadIdx.x & 31;
    if (gw >= 8 * OUT) return;
    int b = gw / OUT, o = gw - b * OUT;
    const float* v = vec + b * 512;
    const float* wr = Wm + (size_t)o * 512;
    float s = 0.f;
#pragma unroll 4
    for (int i = lane; i < 512; i += 32) s = fmaf(v[i], wr[i], s);
#pragma unroll
    for (int off = 16; off; off >>= 1) s += __shfl_xor_sync(0xffffffffu, s, off);
    if (lane == 0) out[b * OUT + o] = s + bias[o];
}

__global__ void __launch_bounds__(256) demod_kernel(
    const float* __restrict__ convw, const float* __restrict__ styles,
    float* __restrict__ demod, int CIN, int COUT) {
    int o = blockIdx.x, tid = threadIdx.x;
    float part[8];
#pragma unroll
    for (int b = 0; b < 8; b++) part[b] = 0.f;
    for (int i = tid; i < CIN; i += 256) {
        const float* wp = convw + ((size_t)o * CIN + i) * 9;
        float wsq = 0.f;
#pragma unroll
        for (int k = 0; k < 9; k++) { float t = wp[k]; wsq = fmaf(t, t, wsq); }
#pragma unroll
        for (int b = 0; b < 8; b++) {
            float s = styles[b * CIN + i];
            part[b] = fmaf(wsq, s * s, part[b]);
        }
    }
    __shared__ float sm[8][9];
#pragma unroll
    for (int b = 0; b < 8; b++)
#pragma unroll
        for (int off = 16; off; off >>= 1)
            part[b] += __shfl_xor_sync(0xffffffffu, part[b], off);
    int warp = tid >> 5, lane = tid & 31;
    if (lane == 0)
        for (int b = 0; b < 8; b++) sm[warp][b] = part[b];
    __syncthreads();
    if (tid < 8) {
        float t = 0.f;
        for (int w2 = 0; w2 < 8; w2++) t += sm[w2][tid];
        demod[tid * COUT + o] = rsqrtf(t + DEMOD_EPS);
    }
}

// weights -> pre-swizzled n-major slice images (single fp16).
__global__ void __launch_bounds__(256) prep_wimg(
    const float* __restrict__ w, __half* __restrict__ BH, int OCB) {
    int idx = blockIdx.x * 256 + threadIdx.x;
    if (idx >= OCB * 36 * 8192) return;
    int k = idx & 63, n = (idx >> 6) & 127, s = (idx >> 13) % 36, ob = idx / (36 * 8192);
    int tap = s >> 2, cb = s & 3;
    float v = w[((size_t)(ob * 128 + n) * 256 + cb * 64 + k) * 9 + tap];
    uint32_t off = n * 64 + (((k >> 3) ^ (n & 7)) << 3) + (k & 7);
    BH[((size_t)ob * 36 + s) * 8192 + off] = __float2half_rn(v);
}

__global__ void zero_border(__half* H, int Hp) {
    int per = 2 * Hp + 2 * (Hp - 2);
    int p = blockIdx.x, c = threadIdx.x;
    int b = p / per, r = p % per;
    int y, x;
    if (r < Hp) { y = 0; x = r; }
    else if (r < 2 * Hp) { y = Hp - 1; x = r - Hp; }
    else { int q = r - 2 * Hp; y = 1 + (q >> 1); x = (q & 1) ? Hp - 1 : 0; }
    H[(((size_t)b * Hp + y) * Hp + x) * 256 + c] = __float2half_rn(0.f);
}

__global__ void __launch_bounds__(256) prep_pad1(
    const float* __restrict__ x, const float* __restrict__ s,
    __half* __restrict__ H) {
    int b = blockIdx.y, y = blockIdx.x, c = threadIdx.x;
    float sc = s[b * 256 + c];
    const float* row = x + ((size_t)(b * 256 + c) * 64 + y) * 64;
    size_t dst = (((size_t)b * 66 + y + 1) * 66 + 1) * 256 + c;
    for (int xx = 0; xx < 64; xx++)
        H[dst + (size_t)xx * 256] = __float2half_rn(row[xx] * sc);
}

__global__ void __launch_bounds__(256) prep_pad2(
    const float* __restrict__ y1, const float* __restrict__ s,
    __half* __restrict__ H) {
    int b = blockIdx.y, yy = blockIdx.x, c = threadIdx.x;
    float sc = s[b * 256 + c];
    int ky = yy >> 1, ylo, yhi; float wy;
    if (yy & 1) { ylo = ky; yhi = (ky + 1 < 64) ? ky + 1 : 63; wy = 0.75f; }
    else        { ylo = (ky > 0) ? ky - 1 : 0; yhi = ky;       wy = 0.25f; }
    const float* base = y1 + (size_t)b * 64 * 64 * 256;
    size_t dst = (((size_t)b * 130 + yy + 1) * 130 + 1) * 256 + c;
    for (int xx = 0; xx < 128; xx++) {
        int kx = xx >> 1, xlo, xhi; float wx;
        if (xx & 1) { xlo = kx; xhi = (kx + 1 < 64) ? kx + 1 : 63; wx = 0.75f; }
        else        { xlo = (kx > 0) ? kx - 1 : 0; xhi = kx;       wx = 0.25f; }
        float v00 = base[((size_t)ylo * 64 + xlo) * 256 + c];
        float v01 = base[((size_t)ylo * 64 + xhi) * 256 + c];
        float v10 = base[((size_t)yhi * 64 + xlo) * 256 + c];
        float v11 = base[((size_t)yhi * 64 + xhi) * 256 + c];
        float v = (wy * (wx * v00 + (1.f - wx) * v01) +
                   (1.f - wy) * (wx * v10 + (1.f - wx) * v11)) * sc;
        H[dst + (size_t)xx * 256] = __float2half_rn(v);
    }
}

// ---------------- mma.sync implicit-GEMM conv --------------------------------
// 128 px x 128 oc per CTA. Single fp16 A and B: D = A·B.
// K = 36 slices of 64. 3-stage cp.async pipeline, 32KB/stage.
// conv2 (NCHW) fuses the toRGB epilogue.
template <int W, int Hp, int COUT, bool NCHW>
__global__ void __launch_bounds__(256, 2) conv_mma(
    const __half* __restrict__ AH, const __half* __restrict__ BHg,
    const float* __restrict__ demod, const float* __restrict__ noise,
    float* __restrict__ out,
    const float* __restrict__ rgb_in, const float* __restrict__ rgb_w,
    const float* __restrict__ rgb_b, float* __restrict__ rgb_out) {
    extern __shared__ char smem[];
    constexpr int LOGW = (W == 64) ? 6 : 7;
    constexpr uint32_t STG = 32768;
    const int tid = threadIdx.x, wid = tid >> 5, lane = tid & 31;
    const int ocb = blockIdx.y, b = blockIdx.z;
    const int y0 = blockIdx.x * (128 / W);
    const uint32_t sbase = smem_u32(smem);

    const int wm = (wid >> 2) * 64;
    const int wn = (wid & 3) * 32;

    const uint32_t a_lane = (((lane >> 3) & 1) << 10) + ((lane & 7) << 7);
    const int a_csel = lane >> 4;
    const uint32_t b_lane = (((lane >> 4) & 1) << 10) + ((lane & 7) << 7);
    const int b_csel = (lane >> 3) & 1;
    const int swz = lane & 7;

    float c[4][4][4];
#pragma unroll
    for (int i = 0; i < 4; i++)
#pragma unroll
        for (int j = 0; j < 4; j++)
#pragma unroll
            for (int v = 0; v < 4; v++) c[i][j][v] = 0.f;

    const size_t bimg = (size_t)ocb * 36 * 8192;

    auto load_slice = [&](int s, int buf) {
        const int tap = s >> 2, cb = s & 3;
        const int dy = tap / 3 - 1, dx = tap % 3 - 1, ci0 = cb * 64;
        const uint32_t base = sbase + buf * STG;
#pragma unroll
        for (int l = 0; l < 4; l++) {
            int i = tid + l * 256;
            int r = i >> 3, q = i & 7;
            int gy = y0 + (r >> LOGW) + dy + 1;
            int gx = (r & (W - 1)) + dx + 1;
            size_t src = (((size_t)b * Hp + gy) * Hp + gx) * 256 + ci0 + q * 8;
            CPA16(base + r * 128 + ((q ^ (r & 7)) << 4), AH + src);
        }
        const char* bh = (const char*)(BHg + bimg + (size_t)s * 8192);
#pragma unroll
        for (int l = 0; l < 4; l++) {
            int i = tid + l * 256;
            CPA16(base + 16384 + i * 16, bh + i * 16);
        }
        CPA_COMMIT();
    };

    load_slice(0, 0);
    load_slice(1, 1);
    for (int s = 0; s < 36; s++) {
        const int buf = s % 3;
        if (s + 2 < 36) {
            load_slice(s + 2, (s + 2) % 3);
            asm volatile("cp.async.wait_group 2;" ::: "memory");
        } else if (s + 1 < 36) {
            asm volatile("cp.async.wait_group 1;" ::: "memory");
        } else {
            asm volatile("cp.async.wait_group 0;" ::: "memory");
        }
        __syncthreads();

        const uint32_t aw = sbase + buf * STG + wm * 128;
        const uint32_t bw = sbase + buf * STG + 16384 + wn * 128;
#pragma unroll
        for (int ks = 0; ks < 4; ks++) {
            uint32_t Ah[4][4], Bh[2][4];
#pragma unroll
            for (int mt = 0; mt < 4; mt++) {
                uint32_t ad = aw + mt * 2048 + a_lane + (((ks * 2 + a_csel) ^ swz) << 4);
                LDSM4(Ah[mt], ad);
            }
#pragma unroll
            for (int q = 0; q < 2; q++) {
                uint32_t bd = bw + q * 2048 + b_lane + (((ks * 2 + b_csel) ^ swz) << 4);
                LDSM4(Bh[q], bd);
            }
#pragma unroll
            for (int mt = 0; mt < 4; mt++)
#pragma unroll
                for (int nt = 0; nt < 4; nt++)
                    MMA16816(c[mt][nt], Ah[mt], (&Bh[nt >> 1][(nt & 1) * 2]));
        }
        __syncthreads();
    }

    // ---- epilogue: stage through smem ---------------------------------------
    float* s_out = (float*)smem;                 // [128 oc][132 px]
    float* sd = s_out + 128 * 132;
    float* sn = sd + 128;
    float* sw = sn + 128;                        // rgb weights [384]
    const int g = lane >> 2, tg = lane & 3;
#pragma unroll
    for (int mt = 0; mt < 4; mt++)
#pragma unroll
        for (int nt = 0; nt < 4; nt++)
#pragma unroll
            for (int v = 0; v < 4; v++) {
                int p = wm + mt * 16 + g + ((v >> 1) << 3);
                int n = wn + nt * 8 + tg * 2 + (v & 1);
                s_out[n * 132 + p] = c[mt][nt][v];
            }
    if (tid < 128) {
        sd[tid] = demod[b * COUT + ocb * 128 + tid];
        sn[tid] = noise[b * COUT + ocb * 128 + tid];
    }
    if (NCHW)
        for (int i = tid; i < 384; i += 256) sw[i] = rgb_w[i];
    __syncthreads();

    if (NCHW) {
        // conv2: out [b][oc][y0][x], W=128, one y-row per block; fused toRGB
        int oc = tid >> 1, xh = tid & 1;
        float d = sd[oc], nz = sn[oc];
        float4* dst = (float4*)(out + (((size_t)(b * COUT + oc) * W + y0) * W + xh * 64));
        float4* srow = (float4*)(s_out + oc * 132 + xh * 64);
#pragma unroll
        for (int j4 = 0; j4 < 16; j4++) {
            float4 v = srow[j4];
            float r0 = fmaf(v.x, d, nz); r0 = (r0 >= 0.f) ? r0 : NEG_SLOPE * r0;
            float r1 = fmaf(v.y, d, nz); r1 = (r1 >= 0.f) ? r1 : NEG_SLOPE * r1;
            float r2 = fmaf(v.z, d, nz); r2 = (r2 >= 0.f) ? r2 : NEG_SLOPE * r2;
            float r3 = fmaf(v.w, d, nz); r3 = (r3 >= 0.f) ? r3 : NEG_SLOPE * r3;
            float4 rv = make_float4(r0, r1, r2, r3);
            dst[j4] = rv;
            srow[j4] = rv;   // keep activated values for rgb stage
        }
        __syncthreads();
        if (tid < 128) {
            int x = tid;
            float a0 = 0.f, a1 = 0.f, a2 = 0.f;
#pragma unroll 4
            for (int o = 0; o < 128; o++) {
                float v = s_out[o * 132 + x];
                a0 = fmaf(v, sw[o], a0);
                a1 = fmaf(v, sw[128 + o], a1);
                a2 = fmaf(v, sw[256 + o], a2);
            }
            float a[3] = {a0, a1, a2};
            int ky = y0 >> 1, kx = x >> 1, ylo, yhi, xlo, xhi;
            float wy, wx;
            if (y0 & 1) { ylo = ky; yhi = (ky + 1 < 64) ? ky + 1 : 63; wy = 0.75f; }
            else        { ylo = (ky > 0) ? ky - 1 : 0; yhi = ky;       wy = 0.25f; }
            if (x & 1)  { xlo = kx; xhi = (kx + 1 < 64) ? kx + 1 : 63; wx = 0.75f; }
            else        { xlo = (kx > 0) ? kx - 1 : 0; xhi = kx;       wx = 0.25f; }
#pragma unroll
            for (int ch = 0; ch < 3; ch++) {
                const float* plane = rgb_in + ((size_t)b * 3 + ch) * 4096;
                float v00 = plane[ylo * 64 + xlo], v01 = plane[ylo * 64 + xhi];
                float v10 = plane[yhi * 64 + xlo], v11 = plane[yhi * 64 + xhi];
                float up = wy * (wx * v00 + (1.f - wx) * v01) +
                           (1.f - wy) * (wx * v10 + (1.f - wx) * v11);
                rgb_out[((size_t)(b * 3 + ch) * 128 + y0) * 128 + x] =
                    (a[ch] + rgb_b[ch] + up) * RES_SCALE;
            }
        }
    } else {
        // conv1: out NHWC [b][y][x][256], W=64, two y-rows per block
        int p = tid >> 1, half = tid & 1;
        int y = y0 + (p >> 6), x = p & 63;
        float* dst = out + (((size_t)(b * 64 + y) * 64 + x) * 256) + ocb * 128 + half * 64;
#pragma unroll
        for (int j = 0; j < 64; j += 4) {
            float vv[4];
#pragma unroll
            for (int e = 0; e < 4; e++) {
                int oc = half * 64 + j + e;
                float v = fmaf(s_out[oc * 132 + p], sd[oc], sn[oc]);
                vv[e] = (v >= 0.f) ? v : NEG_SLOPE * v;
            }
            *(float4*)(dst + j) = make_float4(vv[0], vv[1], vv[2], vv[3]);
        }
    }
}

// ---------------- launcher ---------------------------------------------------
extern "C" void kernel_launch(void* const* d_in, const int* in_sizes, int n_in,
                              void* d_out, int out_size) {
    const float* x       = (const float*)d_in[0];
    const float* w       = (const float*)d_in[1];
    const float* n       = (const float*)d_in[2];
    const float* rgb     = (const float*)d_in[3];
    const float* conv1_w = (const float*)d_in[4];
    const float* A1_w    = (const float*)d_in[5];
    const float* A1_b    = (const float*)d_in[6];
    const float* B1_w    = (const float*)d_in[7];
    const float* B1_b    = (const float*)d_in[8];
    const float* conv2_w = (const float*)d_in[9];
    const float* A2_w    = (const float*)d_in[10];
    const float* A2_b    = (const float*)d_in[11];
    const float* B2_w    = (const float*)d_in[12];
    const float* B2_b    = (const float*)d_in[13];
    const float* rgb_w   = (const float*)d_in[14];
    const float* rgb_b   = (const float*)d_in[15];

    static float* p_y1 = nullptr;
    static __half *p1H, *p2H, *wH1, *wH2;
    static float *p_s1, *p_n1, *p_s2, *p_n2, *p_d1, *p_d2;
    if (!p_y1) {
        cudaGetSymbolAddress((void**)&p_y1, g_y1);
        cudaGetSymbolAddress((void**)&p1H, g_p1H);
        cudaGetSymbolAddress((void**)&p2H, g_p2H);
        cudaGetSymbolAddress((void**)&wH1, g_wH1);
        cudaGetSymbolAddress((void**)&wH2, g_wH2);
        cudaGetSymbolAddress((void**)&p_s1, g_s1);
        cudaGetSymbolAddress((void**)&p_n1, g_n1);
        cudaGetSymbolAddress((void**)&p_s2, g_s2);
        cudaGetSymbolAddress((void**)&p_n2, g_n2);
        cudaGetSymbolAddress((void**)&p_d1, g_d1);
        cudaGetSymbolAddress((void**)&p_d2, g_d2);
        cudaFuncSetAttribute(conv_mma<64, 66, 256, false>,
                             cudaFuncAttributeMaxDynamicSharedMemorySize, 98304);
        cudaFuncSetAttribute(conv_mma<128, 130, 128, true>,
                             cudaFuncAttributeMaxDynamicSharedMemorySize, 98304);
    }

    float* xout = (float*)d_out;                         // [8,128,128,128]
    float* rgbout = xout + (size_t)8 * 128 * 128 * 128;  // [8,3,128,128]

    affine_kernel<<<256, 256>>>(w, A1_w, A1_b, p_s1, 256);
    affine_kernel<<<256, 256>>>(n, B1_w, B1_b, p_n1, 256);
    affine_kernel<<<256, 256>>>(w, A2_w, A2_b, p_s2, 256);
    affine_kernel<<<128, 256>>>(n, B2_w, B2_b, p_n2, 128);
    demod_kernel<<<256, 256>>>(conv1_w, p_s1, p_d1, 256, 256);
    demod_kernel<<<128, 256>>>(conv2_w, p_s2, p_d2, 256, 128);
    prep_wimg<<<(2 * 36 * 8192 + 255) / 256, 256>>>(conv1_w, wH1, 2);
    prep_wimg<<<(1 * 36 * 8192 + 255) / 256, 256>>>(conv2_w, wH2, 1);
    zero_border<<<8 * (2 * 66 + 2 * 64), 256>>>(p1H, 66);
    zero_border<<<8 * (2 * 130 + 2 * 128), 256>>>(p2H, 130);
    prep_pad1<<<dim3(64, 8), 256>>>(x, p_s1, p1H);

    conv_mma<64, 66, 256, false><<<dim3(32, 2, 8), 256, 98304>>>(
        p1H, wH1, p_d1, p_n1, p_y1, nullptr, nullptr, nullptr, nullptr);

    prep_pad2<<<dim3(128, 8), 256>>>(p_y1, p_s2, p2H);

    conv_mma<128, 130, 128, true><<<dim3(128, 1, 8), 256, 98304>>>(
        p2H, wH2, p_d2, p_n2, xout, rgb, rgb_w, rgb_b, rgbout);
}

// round 8
// speedup vs baseline: 6.6758x; 1.0216x over previous
#include <cuda_runtime.h>
#include <cuda_fp16.h>
#include <math.h>
#include <stdint.h>

#define NEG_SLOPE 0.1f
#define RES_SCALE 0.70710678118654752440f
#define DEMOD_EPS 1e-5f

// ---------------- scratch globals (no allocation allowed) -------------------
__device__ __align__(16) float g_y1[8 * 64 * 64 * 256];        // conv1 out NHWC
__device__ __align__(16) __half g_p1H[8 * 66 * 66 * 256];      // styled pad in1
__device__ __align__(16) __half g_p2H[8 * 130 * 130 * 256];    // styled up in2
__device__ __align__(16) __half g_wH1[2 * 36 * 8192];          // pre-swizzled B img
__device__ __align__(16) __half g_wH2[1 * 36 * 8192];
__device__ float g_s1[8 * 256], g_n1[8 * 256], g_s2[8 * 256], g_n2[8 * 128];
__device__ float g_d1[8 * 256], g_d2[8 * 128];

// ---------------- portable PTX helpers ---------------------------------------
__device__ __forceinline__ uint32_t smem_u32(const void* p) {
    uint32_t a;
    asm("{ .reg .u64 t; cvta.to.shared.u64 t, %1; cvt.u32.u64 %0, t; }" : "=r"(a) : "l"(p));
    return a;
}
#define CPA16CG(dst, src) \
    asm volatile("cp.async.cg.shared.global [%0], [%1], 16;" :: "r"(dst), "l"(src))
#define CPA16CA(dst, src) \
    asm volatile("cp.async.ca.shared.global [%0], [%1], 16;" :: "r"(dst), "l"(src))
#define CPA_COMMIT() asm volatile("cp.async.commit_group;" ::: "memory")
#define LDSM4(r, addr) \
    asm volatile("ldmatrix.sync.aligned.m8n8.x4.shared.b16 {%0,%1,%2,%3}, [%4];" \
                 : "=r"((r)[0]), "=r"((r)[1]), "=r"((r)[2]), "=r"((r)[3]) : "r"(addr))
#define MMA16816(c, a, b) \
    asm volatile("mma.sync.aligned.m16n8k16.row.col.f32.f16.f16.f32 " \
                 "{%0,%1,%2,%3},{%4,%5,%6,%7},{%8,%9},{%0,%1,%2,%3};" \
                 : "+f"((c)[0]), "+f"((c)[1]), "+f"((c)[2]), "+f"((c)[3]) \
                 : "r"((a)[0]), "r"((a)[1]), "r"((a)[2]), "r"((a)[3]), \
                   "r"((b)[0]), "r"((b)[1]))

// ---------------- stage 1: affines + weight images + borders (fused) --------
// grid layout: [0,896) affines | [896,4352) wimg | [4352,6432) border1 | [6432,10560) border2
__global__ void __launch_bounds__(256) prep_stage1(
    const float* __restrict__ w, const float* __restrict__ n,
    const float* __restrict__ A1_w, const float* __restrict__ A1_b,
    const float* __restrict__ B1_w, const float* __restrict__ B1_b,
    const float* __restrict__ A2_w, const float* __restrict__ A2_b,
    const float* __restrict__ B2_w, const float* __restrict__ B2_b,
    const float* __restrict__ conv1_w, const float* __restrict__ conv2_w,
    float* __restrict__ s1, float* __restrict__ n1,
    float* __restrict__ s2, float* __restrict__ n2,
    __half* __restrict__ wH1, __half* __restrict__ wH2,
    __half* __restrict__ p1H, __half* __restrict__ p2H) {
    int blk = blockIdx.x;
    if (blk < 896) {
        // ---- 4 affines, one warp per (b, o)
        int gw = (blk * 256 + threadIdx.x) >> 5, lane = threadIdx.x & 31;
        const float *vec, *Wm, *bias; float* out; int OUT, base;
        if (gw < 2048)      { vec = w; Wm = A1_w; bias = A1_b; out = s1; OUT = 256; base = 0; }
        else if (gw < 4096) { vec = n; Wm = B1_w; bias = B1_b; out = n1; OUT = 256; base = 2048; }
        else if (gw < 6144) { vec = w; Wm = A2_w; bias = A2_b; out = s2; OUT = 256; base = 4096; }
        else                { vec = n; Wm = B2_w; bias = B2_b; out = n2; OUT = 128; base = 6144; }
        int t = gw - base, b = t / OUT, o = t - b * OUT;
        const float* v = vec + b * 512;
        const float* wr = Wm + (size_t)o * 512;
        float s = 0.f;
#pragma unroll 4
        for (int i = lane; i < 512; i += 32) s = fmaf(v[i], wr[i], s);
#pragma unroll
        for (int off = 16; off; off >>= 1) s += __shfl_xor_sync(0xffffffffu, s, off);
        if (lane == 0) out[b * OUT + o] = s + bias[o];
    } else if (blk < 4352) {
        // ---- weight images: cb-major slice order s = cb*9 + tap
        int idx = (blk - 896) * 256 + threadIdx.x;   // < 3*36*8192
        int k = idx & 63, nn = (idx >> 6) & 127, s = (idx >> 13) % 36, ob = idx / (36 * 8192);
        int cb = s / 9, tap = s - cb * 9;
        uint32_t off = nn * 64 + (((k >> 3) ^ (nn & 7)) << 3) + (k & 7);
        if (ob < 2) {
            float v = conv1_w[((size_t)(ob * 128 + nn) * 256 + cb * 64 + k) * 9 + tap];
            wH1[((size_t)ob * 36 + s) * 8192 + off] = __float2half_rn(v);
        } else {
            float v = conv2_w[((size_t)nn * 256 + cb * 64 + k) * 9 + tap];
            wH2[(size_t)s * 8192 + off] = __float2half_rn(v);
        }
    } else {
        // ---- zero borders
        __half* H; int Hp, p;
        if (blk < 6432) { H = p1H; Hp = 66; p = blk - 4352; }
        else            { H = p2H; Hp = 130; p = blk - 6432; }
        int per = 2 * Hp + 2 * (Hp - 2);
        int b = p / per, r = p % per, c = threadIdx.x;
        int y, x;
        if (r < Hp) { y = 0; x = r; }
        else if (r < 2 * Hp) { y = Hp - 1; x = r - Hp; }
        else { int q = r - 2 * Hp; y = 1 + (q >> 1); x = (q & 1) ? Hp - 1 : 0; }
        H[(((size_t)b * Hp + y) * Hp + x) * 256 + c] = __float2half_rn(0.f);
    }
}

// ---------------- stage 2: demods + pad1 (fused) -----------------------------
// grid: [0,256) demod1 | [256,384) demod2 | [384,896) pad1
__global__ void __launch_bounds__(256) prep_stage2(
    const float* __restrict__ conv1_w, const float* __restrict__ conv2_w,
    const float* __restrict__ x,
    const float* __restrict__ s1, const float* __restrict__ s2,
    float* __restrict__ d1, float* __restrict__ d2,
    __half* __restrict__ p1H) {
    int blk = blockIdx.x, tid = threadIdx.x;
    if (blk < 384) {
        const float* convw; const float* styles; float* demod; int o, COUT;
        if (blk < 256) { convw = conv1_w; styles = s1; demod = d1; o = blk; COUT = 256; }
        else           { convw = conv2_w; styles = s2; demod = d2; o = blk - 256; COUT = 128; }
        float part[8];
#pragma unroll
        for (int b = 0; b < 8; b++) part[b] = 0.f;
        for (int i = tid; i < 256; i += 256) {
            const float* wp = convw + ((size_t)o * 256 + i) * 9;
            float wsq = 0.f;
#pragma unroll
            for (int k = 0; k < 9; k++) { float t = wp[k]; wsq = fmaf(t, t, wsq); }
#pragma unroll
            for (int b = 0; b < 8; b++) {
                float s = styles[b * 256 + i];
                part[b] = fmaf(wsq, s * s, part[b]);
            }
        }
        __shared__ float sm[8][9];
#pragma unroll
        for (int b = 0; b < 8; b++)
#pragma unroll
            for (int off = 16; off; off >>= 1)
                part[b] += __shfl_xor_sync(0xffffffffu, part[b], off);
        int warp = tid >> 5, lane = tid & 31;
        if (lane == 0)
            for (int b = 0; b < 8; b++) sm[warp][b] = part[b];
        __syncthreads();
        if (tid < 8) {
            float t = 0.f;
            for (int w2 = 0; w2 < 8; w2++) t += sm[w2][tid];
            demod[tid * COUT + o] = rsqrtf(t + DEMOD_EPS);
        }
    } else {
        // pad1: styled x -> padded NHWC fp16
        int p = blk - 384;               // [0,512)
        int b = p >> 6, y = p & 63, c = tid;
        float sc = s1[b * 256 + c];
        const float* row = x + ((size_t)(b * 256 + c) * 64 + y) * 64;
        size_t dst = (((size_t)b * 66 + y + 1) * 66 + 1) * 256 + c;
        for (int xx = 0; xx < 64; xx++)
            p1H[dst + (size_t)xx * 256] = __float2half_rn(row[xx] * sc);
    }
}

// y1 NHWC fp32 -> upsample2x + style2 -> padded NHWC fp16
__global__ void __launch_bounds__(256) prep_pad2(
    const float* __restrict__ y1, const float* __restrict__ s,
    __half* __restrict__ H) {
    int b = blockIdx.y, yy = blockIdx.x, c = threadIdx.x;
    float sc = s[b * 256 + c];
    int ky = yy >> 1, ylo, yhi; float wy;
    if (yy & 1) { ylo = ky; yhi = (ky + 1 < 64) ? ky + 1 : 63; wy = 0.75f; }
    else        { ylo = (ky > 0) ? ky - 1 : 0; yhi = ky;       wy = 0.25f; }
    const float* base = y1 + (size_t)b * 64 * 64 * 256;
    size_t dst = (((size_t)b * 130 + yy + 1) * 130 + 1) * 256 + c;
    for (int xx = 0; xx < 128; xx++) {
        int kx = xx >> 1, xlo, xhi; float wx;
        if (xx & 1) { xlo = kx; xhi = (kx + 1 < 64) ? kx + 1 : 63; wx = 0.75f; }
        else        { xlo = (kx > 0) ? kx - 1 : 0; xhi = kx;       wx = 0.25f; }
        float v00 = base[((size_t)ylo * 64 + xlo) * 256 + c];
        float v01 = base[((size_t)ylo * 64 + xhi) * 256 + c];
        float v10 = base[((size_t)yhi * 64 + xlo) * 256 + c];
        float v11 = base[((size_t)yhi * 64 + xhi) * 256 + c];
        float v = (wy * (wx * v00 + (1.f - wx) * v01) +
                   (1.f - wy) * (wx * v10 + (1.f - wx) * v11)) * sc;
        H[dst + (size_t)xx * 256] = __float2half_rn(v);
    }
}

// ---------------- mma.sync implicit-GEMM conv --------------------------------
// 128 px x 128 oc per CTA. fp16 A,B. K = 36 slices of 64, CB-MAJOR order so
// the per-cb input halo stays L1-resident across its 9 taps (A via cp.async.ca).
// 3-stage cp.async pipeline, 32KB/stage. conv2 (NCHW) fuses toRGB epilogue.
template <int W, int Hp, int COUT, bool NCHW>
__global__ void __launch_bounds__(256, 2) conv_mma(
    const __half* __restrict__ AH, const __half* __restrict__ BHg,
    const float* __restrict__ demod, const float* __restrict__ noise,
    float* __restrict__ out,
    const float* __restrict__ rgb_in, const float* __restrict__ rgb_w,
    const float* __restrict__ rgb_b, float* __restrict__ rgb_out) {
    extern __shared__ char smem[];
    constexpr int LOGW = (W == 64) ? 6 : 7;
    constexpr uint32_t STG = 32768;
    const int tid = threadIdx.x, wid = tid >> 5, lane = tid & 31;
    const int ocb = blockIdx.y, b = blockIdx.z;
    const int y0 = blockIdx.x * (128 / W);
    const uint32_t sbase = smem_u32(smem);

    const int wm = (wid >> 2) * 64;
    const int wn = (wid & 3) * 32;

    const uint32_t a_lane = (((lane >> 3) & 1) << 10) + ((lane & 7) << 7);
    const int a_csel = lane >> 4;
    const uint32_t b_lane = (((lane >> 4) & 1) << 10) + ((lane & 7) << 7);
    const int b_csel = (lane >> 3) & 1;
    const int swz = lane & 7;

    float c[4][4][4];
#pragma unroll
    for (int i = 0; i < 4; i++)
#pragma unroll
        for (int j = 0; j < 4; j++)
#pragma unroll
            for (int v = 0; v < 4; v++) c[i][j][v] = 0.f;

    const size_t bimg = (size_t)ocb * 36 * 8192;

    auto load_slice = [&](int s, int buf) {
        const int cb = s / 9, tap = s - cb * 9;          // cb-major
        const int dy = tap / 3 - 1, dx = tap % 3 - 1, ci0 = cb * 64;
        const uint32_t base = sbase + buf * STG;
#pragma unroll
        for (int l = 0; l < 4; l++) {
            int i = tid + l * 256;
            int r = i >> 3, q = i & 7;
            int gy = y0 + (r >> LOGW) + dy + 1;
            int gx = (r & (W - 1)) + dx + 1;
            size_t src = (((size_t)b * Hp + gy) * Hp + gx) * 256 + ci0 + q * 8;
            CPA16CA(base + r * 128 + ((q ^ (r & 7)) << 4), AH + src);  // L1-cached
        }
        const char* bh = (const char*)(BHg + bimg + (size_t)s * 8192);
#pragma unroll
        for (int l = 0; l < 4; l++) {
            int i = tid + l * 256;
            CPA16CG(base + 16384 + i * 16, bh + i * 16);               // streamed
        }
        CPA_COMMIT();
    };

    load_slice(0, 0);
    load_slice(1, 1);
    for (int s = 0; s < 36; s++) {
        const int buf = s % 3;
        if (s + 2 < 36) {
            load_slice(s + 2, (s + 2) % 3);
            asm volatile("cp.async.wait_group 2;" ::: "memory");
        } else if (s + 1 < 36) {
            asm volatile("cp.async.wait_group 1;" ::: "memory");
        } else {
            asm volatile("cp.async.wait_group 0;" ::: "memory");
        }
        __syncthreads();

        const uint32_t aw = sbase + buf * STG + wm * 128;
        const uint32_t bw = sbase + buf * STG + 16384 + wn * 128;
#pragma unroll
        for (int ks = 0; ks < 4; ks++) {
            uint32_t Ah[4][4], Bh[2][4];
#pragma unroll
            for (int mt = 0; mt < 4; mt++) {
                uint32_t ad = aw + mt * 2048 + a_lane + (((ks * 2 + a_csel) ^ swz) << 4);
                LDSM4(Ah[mt], ad);
            }
#pragma unroll
            for (int q = 0; q < 2; q++) {
                uint32_t bd = bw + q * 2048 + b_lane + (((ks * 2 + b_csel) ^ swz) << 4);
                LDSM4(Bh[q], bd);
            }
#pragma unroll
            for (int mt = 0; mt < 4; mt++)
#pragma unroll
                for (int nt = 0; nt < 4; nt++)
                    MMA16816(c[mt][nt], Ah[mt], (&Bh[nt >> 1][(nt & 1) * 2]));
        }
        __syncthreads();
    }

    // ---- epilogue: stage through smem ---------------------------------------
    float* s_out = (float*)smem;                 // [128 oc][132 px]
    float* sd = s_out + 128 * 132;
    float* sn = sd + 128;
    float* sw = sn + 128;                        // rgb weights [384]
    const int g = lane >> 2, tg = lane & 3;
#pragma unroll
    for (int mt = 0; mt < 4; mt++)
#pragma unroll
        for (int nt = 0; nt < 4; nt++)
#pragma unroll
            for (int v = 0; v < 4; v++) {
                int p = wm + mt * 16 + g + ((v >> 1) << 3);
                int n = wn + nt * 8 + tg * 2 + (v & 1);
                s_out[n * 132 + p] = c[mt][nt][v];
            }
    if (tid < 128) {
        sd[tid] = demod[b * COUT + ocb * 128 + tid];
        sn[tid] = noise[b * COUT + ocb * 128 + tid];
    }
    if (NCHW)
        for (int i = tid; i < 384; i += 256) sw[i] = rgb_w[i];
    __syncthreads();

    if (NCHW) {
        // conv2: out [b][oc][y0][x], W=128, one y-row per block; fused toRGB
        int oc = tid >> 1, xh = tid & 1;
        float d = sd[oc], nz = sn[oc];
        float4* dst = (float4*)(out + (((size_t)(b * COUT + oc) * W + y0) * W + xh * 64));
        float4* srow = (float4*)(s_out + oc * 132 + xh * 64);
#pragma unroll
        for (int j4 = 0; j4 < 16; j4++) {
            float4 v = srow[j4];
            float r0 = fmaf(v.x, d, nz); r0 = (r0 >= 0.f) ? r0 : NEG_SLOPE * r0;
            float r1 = fmaf(v.y, d, nz); r1 = (r1 >= 0.f) ? r1 : NEG_SLOPE * r1;
            float r2 = fmaf(v.z, d, nz); r2 = (r2 >= 0.f) ? r2 : NEG_SLOPE * r2;
            float r3 = fmaf(v.w, d, nz); r3 = (r3 >= 0.f) ? r3 : NEG_SLOPE * r3;
            float4 rv = make_float4(r0, r1, r2, r3);
            dst[j4] = rv;
            srow[j4] = rv;   // keep activated values for rgb stage
        }
        __syncthreads();
        if (tid < 128) {
            int x = tid;
            float a0 = 0.f, a1 = 0.f, a2 = 0.f;
#pragma unroll 4
            for (int o = 0; o < 128; o++) {
                float v = s_out[o * 132 + x];
                a0 = fmaf(v, sw[o], a0);
                a1 = fmaf(v, sw[128 + o], a1);
                a2 = fmaf(v, sw[256 + o], a2);
            }
            float a[3] = {a0, a1, a2};
            int ky = y0 >> 1, kx = x >> 1, ylo, yhi, xlo, xhi;
            float wy, wx;
            if (y0 & 1) { ylo = ky; yhi = (ky + 1 < 64) ? ky + 1 : 63; wy = 0.75f; }
            else        { ylo = (ky > 0) ? ky - 1 : 0; yhi = ky;       wy = 0.25f; }
            if (x & 1)  { xlo = kx; xhi = (kx + 1 < 64) ? kx + 1 : 63; wx = 0.75f; }
            else        { xlo = (kx > 0) ? kx - 1 : 0; xhi = kx;       wx = 0.25f; }
#pragma unroll
            for (int ch = 0; ch < 3; ch++) {
                const float* plane = rgb_in + ((size_t)b * 3 + ch) * 4096;
                float v00 = plane[ylo * 64 + xlo], v01 = plane[ylo * 64 + xhi];
                float v10 = plane[yhi * 64 + xlo], v11 = plane[yhi * 64 + xhi];
                float up = wy * (wx * v00 + (1.f - wx) * v01) +
                           (1.f - wy) * (wx * v10 + (1.f - wx) * v11);
                rgb_out[((size_t)(b * 3 + ch) * 128 + y0) * 128 + x] =
                    (a[ch] + rgb_b[ch] + up) * RES_SCALE;
            }
        }
    } else {
        // conv1: out NHWC [b][y][x][256], W=64, two y-rows per block
        int p = tid >> 1, half = tid & 1;
        int y = y0 + (p >> 6), x = p & 63;
        float* dst = out + (((size_t)(b * 64 + y) * 64 + x) * 256) + ocb * 128 + half * 64;
#pragma unroll
        for (int j = 0; j < 64; j += 4) {
            float vv[4];
#pragma unroll
            for (int e = 0; e < 4; e++) {
                int oc = half * 64 + j + e;
                float v = fmaf(s_out[oc * 132 + p], sd[oc], sn[oc]);
                vv[e] = (v >= 0.f) ? v : NEG_SLOPE * v;
            }
            *(float4*)(dst + j) = make_float4(vv[0], vv[1], vv[2], vv[3]);
        }
    }
}

// ---------------- launcher ---------------------------------------------------
extern "C" void kernel_launch(void* const* d_in, const int* in_sizes, int n_in,
                              void* d_out, int out_size) {
    const float* x       = (const float*)d_in[0];
    const float* w       = (const float*)d_in[1];
    const float* n       = (const float*)d_in[2];
    const float* rgb     = (const float*)d_in[3];
    const float* conv1_w = (const float*)d_in[4];
    const float* A1_w    = (const float*)d_in[5];
    const float* A1_b    = (const float*)d_in[6];
    const float* B1_w    = (const float*)d_in[7];
    const float* B1_b    = (const float*)d_in[8];
    const float* conv2_w = (const float*)d_in[9];
    const float* A2_w    = (const float*)d_in[10];
    const float* A2_b    = (const float*)d_in[11];
    const float* B2_w    = (const float*)d_in[12];
    const float* B2_b    = (const float*)d_in[13];
    const float* rgb_w   = (const float*)d_in[14];
    const float* rgb_b   = (const float*)d_in[15];

    static float* p_y1 = nullptr;
    static __half *p1H, *p2H, *wH1, *wH2;
    static float *p_s1, *p_n1, *p_s2, *p_n2, *p_d1, *p_d2;
    if (!p_y1) {
        cudaGetSymbolAddress((void**)&p_y1, g_y1);
        cudaGetSymbolAddress((void**)&p1H, g_p1H);
        cudaGetSymbolAddress((void**)&p2H, g_p2H);
        cudaGetSymbolAddress((void**)&wH1, g_wH1);
        cudaGetSymbolAddress((void**)&wH2, g_wH2);
        cudaGetSymbolAddress((void**)&p_s1, g_s1);
        cudaGetSymbolAddress((void**)&p_n1, g_n1);
        cudaGetSymbolAddress((void**)&p_s2, g_s2);
        cudaGetSymbolAddress((void**)&p_n2, g_n2);
        cudaGetSymbolAddress((void**)&p_d1, g_d1);
        cudaGetSymbolAddress((void**)&p_d2, g_d2);
        cudaFuncSetAttribute(conv_mma<64, 66, 256, false>,
                             cudaFuncAttributeMaxDynamicSharedMemorySize, 98304);
        cudaFuncSetAttribute(conv_mma<128, 130, 128, true>,
                             cudaFuncAttributeMaxDynamicSharedMemorySize, 98304);
    }

    float* xout = (float*)d_out;                         // [8,128,128,128]
    float* rgbout = xout + (size_t)8 * 128 * 128 * 128;  // [8,3,128,128]

    // stage1: affines + weight images + borders (all independent, one grid)
    prep_stage1<<<10560, 256>>>(w, n, A1_w, A1_b, B1_w, B1_b, A2_w, A2_b,
                                B2_w, B2_b, conv1_w, conv2_w,
                                p_s1, p_n1, p_s2, p_n2, wH1, wH2, p1H, p2H);
    // stage2: demods + pad1 (need styles)
    prep_stage2<<<896, 256>>>(conv1_w, conv2_w, x, p_s1, p_s2, p_d1, p_d2, p1H);

    conv_mma<64, 66, 256, false><<<dim3(32, 2, 8), 256, 98304>>>(
        p1H, wH1, p_d1, p_n1, p_y1, nullptr, nullptr, nullptr, nullptr);

    prep_pad2<<<dim3(128, 8), 256>>>(p_y1, p_s2, p2H);

    conv_mma<128, 130, 128, true><<<dim3(128, 1, 8), 256, 98304>>>(
        p2H, wH2, p_d2, p_n2, xout, rgb, rgb_w, rgb_b, rgbout);
}

// round 9
// speedup vs baseline: 7.1797x; 1.0755x over previous
#include <cuda_runtime.h>
#include <cuda_fp16.h>
#include <math.h>
#include <stdint.h>

#define NEG_SLOPE 0.1f
#define RES_SCALE 0.70710678118654752440f
#define DEMOD_EPS 1e-5f

// ---------------- scratch globals (no allocation allowed) -------------------
__device__ __align__(16) float g_y1[8 * 64 * 64 * 256];        // conv1 out NHWC
__device__ __align__(16) __half g_p1H[8 * 66 * 66 * 256];      // styled pad in1
__device__ __align__(16) __half g_p2H[8 * 130 * 130 * 256];    // styled up in2
__device__ __align__(16) __half g_wH1[2 * 36 * 8192];          // pre-swizzled B img
__device__ __align__(16) __half g_wH2[1 * 36 * 8192];
__device__ float g_s1[8 * 256], g_n1[8 * 256], g_s2[8 * 256], g_n2[8 * 128];
__device__ float g_d1[8 * 256], g_d2[8 * 128];

// ---------------- portable PTX helpers ---------------------------------------
__device__ __forceinline__ uint32_t smem_u32(const void* p) {
    uint32_t a;
    asm("{ .reg .u64 t; cvta.to.shared.u64 t, %1; cvt.u32.u64 %0, t; }" : "=r"(a) : "l"(p));
    return a;
}
#define CPA16CG(dst, src) \
    asm volatile("cp.async.cg.shared.global [%0], [%1], 16;" :: "r"(dst), "l"(src))
#define CPA16CA(dst, src) \
    asm volatile("cp.async.ca.shared.global [%0], [%1], 16;" :: "r"(dst), "l"(src))
#define CPA_COMMIT() asm volatile("cp.async.commit_group;" ::: "memory")
#define LDSM4(r, addr) \
    asm volatile("ldmatrix.sync.aligned.m8n8.x4.shared.b16 {%0,%1,%2,%3}, [%4];" \
                 : "=r"((r)[0]), "=r"((r)[1]), "=r"((r)[2]), "=r"((r)[3]) : "r"(addr))
#define MMA16816(c, a, b) \
    asm volatile("mma.sync.aligned.m16n8k16.row.col.f32.f16.f16.f32 " \
                 "{%0,%1,%2,%3},{%4,%5,%6,%7},{%8,%9},{%0,%1,%2,%3};" \
                 : "+f"((c)[0]), "+f"((c)[1]), "+f"((c)[2]), "+f"((c)[3]) \
                 : "r"((a)[0]), "r"((a)[1]), "r"((a)[2]), "r"((a)[3]), \
                   "r"((b)[0]), "r"((b)[1]))

// ---------------- stage 1: affines + weight images + borders (fused) --------
__global__ void __launch_bounds__(256) prep_stage1(
    const float* __restrict__ w, const float* __restrict__ n,
    const float* __restrict__ A1_w, const float* __restrict__ A1_b,
    const float* __restrict__ B1_w, const float* __restrict__ B1_b,
    const float* __restrict__ A2_w, const float* __restrict__ A2_b,
    const float* __restrict__ B2_w, const float* __restrict__ B2_b,
    const float* __restrict__ conv1_w, const float* __restrict__ conv2_w,
    float* __restrict__ s1, float* __restrict__ n1,
    float* __restrict__ s2, float* __restrict__ n2,
    __half* __restrict__ wH1, __half* __restrict__ wH2,
    __half* __restrict__ p1H, __half* __restrict__ p2H) {
    int blk = blockIdx.x;
    if (blk < 896) {
        int gw = (blk * 256 + threadIdx.x) >> 5, lane = threadIdx.x & 31;
        const float *vec, *Wm, *bias; float* out; int OUT, base;
        if (gw < 2048)      { vec = w; Wm = A1_w; bias = A1_b; out = s1; OUT = 256; base = 0; }
        else if (gw < 4096) { vec = n; Wm = B1_w; bias = B1_b; out = n1; OUT = 256; base = 2048; }
        else if (gw < 6144) { vec = w; Wm = A2_w; bias = A2_b; out = s2; OUT = 256; base = 4096; }
        else                { vec = n; Wm = B2_w; bias = B2_b; out = n2; OUT = 128; base = 6144; }
        int t = gw - base, b = t / OUT, o = t - b * OUT;
        const float* v = vec + b * 512;
        const float* wr = Wm + (size_t)o * 512;
        float s = 0.f;
#pragma unroll 4
        for (int i = lane; i < 512; i += 32) s = fmaf(v[i], wr[i], s);
#pragma unroll
        for (int off = 16; off; off >>= 1) s += __shfl_xor_sync(0xffffffffu, s, off);
        if (lane == 0) out[b * OUT + o] = s + bias[o];
    } else if (blk < 4352) {
        int idx = (blk - 896) * 256 + threadIdx.x;
        int k = idx & 63, nn = (idx >> 6) & 127, s = (idx >> 13) % 36, ob = idx / (36 * 8192);
        int cb = s / 9, tap = s - cb * 9;
        uint32_t off = nn * 64 + (((k >> 3) ^ (nn & 7)) << 3) + (k & 7);
        if (ob < 2) {
            float v = conv1_w[((size_t)(ob * 128 + nn) * 256 + cb * 64 + k) * 9 + tap];
            wH1[((size_t)ob * 36 + s) * 8192 + off] = __float2half_rn(v);
        } else {
            float v = conv2_w[((size_t)nn * 256 + cb * 64 + k) * 9 + tap];
            wH2[(size_t)s * 8192 + off] = __float2half_rn(v);
        }
    } else {
        __half* H; int Hp, p;
        if (blk < 6432) { H = p1H; Hp = 66; p = blk - 4352; }
        else            { H = p2H; Hp = 130; p = blk - 6432; }
        int per = 2 * Hp + 2 * (Hp - 2);
        int b = p / per, r = p % per, c = threadIdx.x;
        int y, x;
        if (r < Hp) { y = 0; x = r; }
        else if (r < 2 * Hp) { y = Hp - 1; x = r - Hp; }
        else { int q = r - 2 * Hp; y = 1 + (q >> 1); x = (q & 1) ? Hp - 1 : 0; }
        H[(((size_t)b * Hp + y) * Hp + x) * 256 + c] = __float2half_rn(0.f);
    }
}

// ---------------- stage 2: demods + pad1 (fused) -----------------------------
__global__ void __launch_bounds__(256) prep_stage2(
    const float* __restrict__ conv1_w, const float* __restrict__ conv2_w,
    const float* __restrict__ x,
    const float* __restrict__ s1, const float* __restrict__ s2,
    float* __restrict__ d1, float* __restrict__ d2,
    __half* __restrict__ p1H) {
    int blk = blockIdx.x, tid = threadIdx.x;
    if (blk < 384) {
        const float* convw; const float* styles; float* demod; int o, COUT;
        if (blk < 256) { convw = conv1_w; styles = s1; demod = d1; o = blk; COUT = 256; }
        else           { convw = conv2_w; styles = s2; demod = d2; o = blk - 256; COUT = 128; }
        float part[8];
#pragma unroll
        for (int b = 0; b < 8; b++) part[b] = 0.f;
        for (int i = tid; i < 256; i += 256) {
            const float* wp = convw + ((size_t)o * 256 + i) * 9;
            float wsq = 0.f;
#pragma unroll
            for (int k = 0; k < 9; k++) { float t = wp[k]; wsq = fmaf(t, t, wsq); }
#pragma unroll
            for (int b = 0; b < 8; b++) {
                float s = styles[b * 256 + i];
                part[b] = fmaf(wsq, s * s, part[b]);
            }
        }
        __shared__ float sm[8][9];
#pragma unroll
        for (int b = 0; b < 8; b++)
#pragma unroll
            for (int off = 16; off; off >>= 1)
                part[b] += __shfl_xor_sync(0xffffffffu, part[b], off);
        int warp = tid >> 5, lane = tid & 31;
        if (lane == 0)
            for (int b = 0; b < 8; b++) sm[warp][b] = part[b];
        __syncthreads();
        if (tid < 8) {
            float t = 0.f;
            for (int w2 = 0; w2 < 8; w2++) t += sm[w2][tid];
            demod[tid * COUT + o] = rsqrtf(t + DEMOD_EPS);
        }
    } else {
        int p = blk - 384;
        int b = p >> 6, y = p & 63, c = tid;
        float sc = s1[b * 256 + c];
        const float* row = x + ((size_t)(b * 256 + c) * 64 + y) * 64;
        size_t dst = (((size_t)b * 66 + y + 1) * 66 + 1) * 256 + c;
        for (int xx = 0; xx < 64; xx++)
            p1H[dst + (size_t)xx * 256] = __float2half_rn(row[xx] * sc);
    }
}

// y1 NHWC fp32 -> upsample2x + style2 -> padded NHWC fp16 (column-sliding)
__global__ void __launch_bounds__(256) prep_pad2(
    const float* __restrict__ y1, const float* __restrict__ s,
    __half* __restrict__ H) {
    int b = blockIdx.y, yy = blockIdx.x, c = threadIdx.x;
    float sc = s[b * 256 + c];
    int ky = yy >> 1, ylo, yhi; float wy;
    if (yy & 1) { ylo = ky; yhi = (ky + 1 < 64) ? ky + 1 : 63; wy = 0.75f; }
    else        { ylo = (ky > 0) ? ky - 1 : 0; yhi = ky;       wy = 0.25f; }
    const float* lo = y1 + (((size_t)b * 64 + ylo) * 64) * 256 + c;
    const float* hi = y1 + (((size_t)b * 64 + yhi) * 64) * 256 + c;
    __half* dst = H + (((size_t)b * 130 + yy + 1) * 130 + 1) * 256 + c;
    float wyc = 1.f - wy;
    // blended column value cl(k) = wy*lo[k] + (1-wy)*hi[k]; slide prev/cur/next
    float ccur = fmaf(wy, lo[0], wyc * hi[0]);
    float cprev = ccur;                 // clamp kx-1 -> 0
#pragma unroll 4
    for (int kx = 0; kx < 64; kx++) {
        float cnext = (kx + 1 < 64)
            ? fmaf(wy, lo[(kx + 1) * 256], wyc * hi[(kx + 1) * 256]) : ccur;
        dst[(size_t)(2 * kx) * 256]     = __float2half_rn((0.25f * cprev + 0.75f * ccur) * sc);
        dst[(size_t)(2 * kx + 1) * 256] = __float2half_rn((0.75f * ccur + 0.25f * cnext) * sc);
        cprev = ccur; ccur = cnext;
    }
}

// ---------------- mma.sync implicit-GEMM conv --------------------------------
// 128 px x 128 oc per CTA, 4 warps, 64x64 warp tile (128 acc regs/thread).
// fp16 A,B single precision term. K = 36 slices of 64, cb-major.
// 3-stage cp.async pipeline, 32KB/stage. conv2 (NCHW) fuses toRGB epilogue.
template <int W, int Hp, int COUT, bool NCHW>
__global__ void __launch_bounds__(128, 2) conv_mma(
    const __half* __restrict__ AH, const __half* __restrict__ BHg,
    const float* __restrict__ demod, const float* __restrict__ noise,
    float* __restrict__ out,
    const float* __restrict__ rgb_in, const float* __restrict__ rgb_w,
    const float* __restrict__ rgb_b, float* __restrict__ rgb_out) {
    extern __shared__ char smem[];
    constexpr int LOGW = (W == 64) ? 6 : 7;
    constexpr uint32_t STG = 32768;
    const int tid = threadIdx.x, wid = tid >> 5, lane = tid & 31;
    const int ocb = blockIdx.y, b = blockIdx.z;
    const int y0 = blockIdx.x * (128 / W);
    const uint32_t sbase = smem_u32(smem);

    const int wm = (wid >> 1) * 64;   // warp pixel offset (0/64)
    const int wn = (wid & 1) * 64;    // warp oc offset   (0/64)

    const uint32_t a_lane = (((lane >> 3) & 1) << 10) + ((lane & 7) << 7);
    const int a_csel = lane >> 4;
    const uint32_t b_lane = (((lane >> 4) & 1) << 10) + ((lane & 7) << 7);
    const int b_csel = (lane >> 3) & 1;
    const int swz = lane & 7;

    float c[4][8][4];
#pragma unroll
    for (int i = 0; i < 4; i++)
#pragma unroll
        for (int j = 0; j < 8; j++)
#pragma unroll
            for (int v = 0; v < 4; v++) c[i][j][v] = 0.f;

    const size_t bimg = (size_t)ocb * 36 * 8192;

    auto load_slice = [&](int s, int buf) {
        const int cb = s / 9, tap = s - cb * 9;
        const int dy = tap / 3 - 1, dx = tap % 3 - 1, ci0 = cb * 64;
        const uint32_t base = sbase + buf * STG;
#pragma unroll
        for (int l = 0; l < 8; l++) {
            int i = tid + l * 128;          // 0..1023
            int r = i >> 3, q = i & 7;
            int gy = y0 + (r >> LOGW) + dy + 1;
            int gx = (r & (W - 1)) + dx + 1;
            size_t src = (((size_t)b * Hp + gy) * Hp + gx) * 256 + ci0 + q * 8;
            CPA16CA(base + r * 128 + ((q ^ (r & 7)) << 4), AH + src);
        }
        const char* bh = (const char*)(BHg + bimg + (size_t)s * 8192);
#pragma unroll
        for (int l = 0; l < 8; l++) {
            int i = tid + l * 128;
            CPA16CG(base + 16384 + i * 16, bh + i * 16);
        }
        CPA_COMMIT();
    };

    load_slice(0, 0);
    load_slice(1, 1);
    for (int s = 0; s < 36; s++) {
        const int buf = s % 3;
        if (s + 2 < 36) {
            load_slice(s + 2, (s + 2) % 3);
            asm volatile("cp.async.wait_group 2;" ::: "memory");
        } else if (s + 1 < 36) {
            asm volatile("cp.async.wait_group 1;" ::: "memory");
        } else {
            asm volatile("cp.async.wait_group 0;" ::: "memory");
        }
        __syncthreads();

        const uint32_t aw = sbase + buf * STG + wm * 128;
        const uint32_t bw = sbase + buf * STG + 16384 + wn * 128;
#pragma unroll
        for (int ks = 0; ks < 4; ks++) {
            uint32_t Ah[4][4], Bh[4][4];
#pragma unroll
            for (int mt = 0; mt < 4; mt++) {
                uint32_t ad = aw + mt * 2048 + a_lane + (((ks * 2 + a_csel) ^ swz) << 4);
                LDSM4(Ah[mt], ad);
            }
#pragma unroll
            for (int q = 0; q < 4; q++) {
                uint32_t bd = bw + q * 2048 + b_lane + (((ks * 2 + b_csel) ^ swz) << 4);
                LDSM4(Bh[q], bd);
            }
#pragma unroll
            for (int mt = 0; mt < 4; mt++)
#pragma unroll
                for (int nt = 0; nt < 8; nt++)
                    MMA16816(c[mt][nt], Ah[mt], (&Bh[nt >> 1][(nt & 1) * 2]));
        }
        __syncthreads();
    }

    // ---- epilogue: stage through smem ---------------------------------------
    float* s_out = (float*)smem;                 // [128 oc][132 px]
    float* sd = s_out + 128 * 132;
    float* sn = sd + 128;
    float* sw = sn + 128;                        // rgb weights [384]
    const int g = lane >> 2, tg = lane & 3;
#pragma unroll
    for (int mt = 0; mt < 4; mt++)
#pragma unroll
        for (int nt = 0; nt < 8; nt++)
#pragma unroll
            for (int v = 0; v < 4; v++) {
                int p = wm + mt * 16 + g + ((v >> 1) << 3);
                int n = wn + nt * 8 + tg * 2 + (v & 1);
                s_out[n * 132 + p] = c[mt][nt][v];
            }
    sd[tid] = demod[b * COUT + ocb * 128 + tid];
    sn[tid] = noise[b * COUT + ocb * 128 + tid];
    if (NCHW)
        for (int i = tid; i < 384; i += 128) sw[i] = rgb_w[i];
    __syncthreads();

    if (NCHW) {
        // conv2: out [b][oc][y0][x], W=128, one y-row per block; fused toRGB
        int oc = tid;
        float d = sd[oc], nz = sn[oc];
        float4* dst = (float4*)(out + (((size_t)(b * COUT + oc) * W + y0) * W));
        float4* srow = (float4*)(s_out + oc * 132);
#pragma unroll
        for (int j4 = 0; j4 < 32; j4++) {
            float4 v = srow[j4];
            float r0 = fmaf(v.x, d, nz); r0 = (r0 >= 0.f) ? r0 : NEG_SLOPE * r0;
            float r1 = fmaf(v.y, d, nz); r1 = (r1 >= 0.f) ? r1 : NEG_SLOPE * r1;
            float r2 = fmaf(v.z, d, nz); r2 = (r2 >= 0.f) ? r2 : NEG_SLOPE * r2;
            float r3 = fmaf(v.w, d, nz); r3 = (r3 >= 0.f) ? r3 : NEG_SLOPE * r3;
            float4 rv = make_float4(r0, r1, r2, r3);
            dst[j4] = rv;
            srow[j4] = rv;   // keep activated values for rgb stage
        }
        __syncthreads();
        {
            int x = tid;
            float a0 = 0.f, a1 = 0.f, a2 = 0.f;
#pragma unroll 4
            for (int o = 0; o < 128; o++) {
                float v = s_out[o * 132 + x];
                a0 = fmaf(v, sw[o], a0);
                a1 = fmaf(v, sw[128 + o], a1);
                a2 = fmaf(v, sw[256 + o], a2);
            }
            float a[3] = {a0, a1, a2};
            int ky = y0 >> 1, kx = x >> 1, ylo, yhi, xlo, xhi;
            float wy, wx;
            if (y0 & 1) { ylo = ky; yhi = (ky + 1 < 64) ? ky + 1 : 63; wy = 0.75f; }
            else        { ylo = (ky > 0) ? ky - 1 : 0; yhi = ky;       wy = 0.25f; }
            if (x & 1)  { xlo = kx; xhi = (kx + 1 < 64) ? kx + 1 : 63; wx = 0.75f; }
            else        { xlo = (kx > 0) ? kx - 1 : 0; xhi = kx;       wx = 0.25f; }
#pragma unroll
            for (int ch = 0; ch < 3; ch++) {
                const float* plane = rgb_in + ((size_t)b * 3 + ch) * 4096;
                float v00 = plane[ylo * 64 + xlo], v01 = plane[ylo * 64 + xhi];
                float v10 = plane[yhi * 64 + xlo], v11 = plane[yhi * 64 + xhi];
                float up = wy * (wx * v00 + (1.f - wx) * v01) +
                           (1.f - wy) * (wx * v10 + (1.f - wx) * v11);
                rgb_out[((size_t)(b * 3 + ch) * 128 + y0) * 128 + x] =
                    (a[ch] + rgb_b[ch] + up) * RES_SCALE;
            }
        }
    } else {
        // conv1: out NHWC [b][y][x][256], W=64, two y-rows; p = tid (1 pixel)
        int p = tid;
        int y = y0 + (p >> 6), x = p & 63;
        float* dst = out + (((size_t)(b * 64 + y) * 64 + x) * 256) + ocb * 128;
#pragma unroll
        for (int j = 0; j < 128; j += 4) {
            float vv[4];
#pragma unroll
            for (int e = 0; e < 4; e++) {
                int oc = j + e;
                float v = fmaf(s_out[oc * 132 + p], sd[oc], sn[oc]);
                vv[e] = (v >= 0.f) ? v : NEG_SLOPE * v;
            }
            *(float4*)(dst + j) = make_float4(vv[0], vv[1], vv[2], vv[3]);
        }
    }
}

// ---------------- launcher ---------------------------------------------------
extern "C" void kernel_launch(void* const* d_in, const int* in_sizes, int n_in,
                              void* d_out, int out_size) {
    const float* x       = (const float*)d_in[0];
    const float* w       = (const float*)d_in[1];
    const float* n       = (const float*)d_in[2];
    const float* rgb     = (const float*)d_in[3];
    const float* conv1_w = (const float*)d_in[4];
    const float* A1_w    = (const float*)d_in[5];
    const float* A1_b    = (const float*)d_in[6];
    const float* B1_w    = (const float*)d_in[7];
    const float* B1_b    = (const float*)d_in[8];
    const float* conv2_w = (const float*)d_in[9];
    const float* A2_w    = (const float*)d_in[10];
    const float* A2_b    = (const float*)d_in[11];
    const float* B2_w    = (const float*)d_in[12];
    const float* B2_b    = (const float*)d_in[13];
    const float* rgb_w   = (const float*)d_in[14];
    const float* rgb_b   = (const float*)d_in[15];

    static float* p_y1 = nullptr;
    static __half *p1H, *p2H, *wH1, *wH2;
    static float *p_s1, *p_n1, *p_s2, *p_n2, *p_d1, *p_d2;
    if (!p_y1) {
        cudaGetSymbolAddress((void**)&p_y1, g_y1);
        cudaGetSymbolAddress((void**)&p1H, g_p1H);
        cudaGetSymbolAddress((void**)&p2H, g_p2H);
        cudaGetSymbolAddress((void**)&wH1, g_wH1);
        cudaGetSymbolAddress((void**)&wH2, g_wH2);
        cudaGetSymbolAddress((void**)&p_s1, g_s1);
        cudaGetSymbolAddress((void**)&p_n1, g_n1);
        cudaGetSymbolAddress((void**)&p_s2, g_s2);
        cudaGetSymbolAddress((void**)&p_n2, g_n2);
        cudaGetSymbolAddress((void**)&p_d1, g_d1);
        cudaGetSymbolAddress((void**)&p_d2, g_d2);
        cudaFuncSetAttribute(conv_mma<64, 66, 256, false>,
                             cudaFuncAttributeMaxDynamicSharedMemorySize, 98304);
        cudaFuncSetAttribute(conv_mma<128, 130, 128, true>,
                             cudaFuncAttributeMaxDynamicSharedMemorySize, 98304);
    }

    float* xout = (float*)d_out;                         // [8,128,128,128]
    float* rgbout = xout + (size_t)8 * 128 * 128 * 128;  // [8,3,128,128]

    prep_stage1<<<10560, 256>>>(w, n, A1_w, A1_b, B1_w, B1_b, A2_w, A2_b,
                                B2_w, B2_b, conv1_w, conv2_w,
                                p_s1, p_n1, p_s2, p_n2, wH1, wH2, p1H, p2H);
    prep_stage2<<<896, 256>>>(conv1_w, conv2_w, x, p_s1, p_s2, p_d1, p_d2, p1H);

    conv_mma<64, 66, 256, false><<<dim3(32, 2, 8), 128, 98304>>>(
        p1H, wH1, p_d1, p_n1, p_y1, nullptr, nullptr, nullptr, nullptr);

    prep_pad2<<<dim3(128, 8), 256>>>(p_y1, p_s2, p2H);

    conv_mma<128, 130, 128, true><<<dim3(128, 1, 8), 128, 98304>>>(
        p2H, wH2, p_d2, p_n2, xout, rgb, rgb_w, rgb_b, rgbout);
}

// round 10
// speedup vs baseline: 7.6167x; 1.0609x over previous
#include <cuda_runtime.h>
#include <cuda_fp16.h>
#include <math.h>
#include <stdint.h>

#define NEG_SLOPE 0.1f
#define RES_SCALE 0.70710678118654752440f
#define DEMOD_EPS 1e-5f

// ---------------- scratch globals (no allocation allowed) -------------------
__device__ __align__(16) float g_y1[8 * 64 * 64 * 256];        // conv1 out NHWC
__device__ __align__(16) __half g_p1H[8 * 66 * 66 * 256];      // styled pad in1
__device__ __align__(16) __half g_p2H[8 * 130 * 130 * 256];    // styled up in2
__device__ __align__(16) __half g_wH1[2 * 36 * 8192];          // pre-swizzled B img
__device__ __align__(16) __half g_wH2[1 * 36 * 8192];
__device__ float g_s1[8 * 256], g_n1[8 * 256], g_s2[8 * 256], g_n2[8 * 128];
__device__ float g_d1[8 * 256], g_d2[8 * 128];

// ---------------- portable PTX helpers ---------------------------------------
__device__ __forceinline__ uint32_t smem_u32(const void* p) {
    uint32_t a;
    asm("{ .reg .u64 t; cvta.to.shared.u64 t, %1; cvt.u32.u64 %0, t; }" : "=r"(a) : "l"(p));
    return a;
}
#define CPA16CG(dst, src) \
    asm volatile("cp.async.cg.shared.global [%0], [%1], 16;" :: "r"(dst), "l"(src))
#define CPA16CA(dst, src) \
    asm volatile("cp.async.ca.shared.global [%0], [%1], 16;" :: "r"(dst), "l"(src))
#define CPA_COMMIT() asm volatile("cp.async.commit_group;" ::: "memory")
#define LDSM4(r, addr) \
    asm volatile("ldmatrix.sync.aligned.m8n8.x4.shared.b16 {%0,%1,%2,%3}, [%4];" \
                 : "=r"((r)[0]), "=r"((r)[1]), "=r"((r)[2]), "=r"((r)[3]) : "r"(addr))
#define MMA16816(c, a, b) \
    asm volatile("mma.sync.aligned.m16n8k16.row.col.f32.f16.f16.f32 " \
                 "{%0,%1,%2,%3},{%4,%5,%6,%7},{%8,%9},{%0,%1,%2,%3};" \
                 : "+f"((c)[0]), "+f"((c)[1]), "+f"((c)[2]), "+f"((c)[3]) \
                 : "r"((a)[0]), "r"((a)[1]), "r"((a)[2]), "r"((a)[3]), \
                   "r"((b)[0]), "r"((b)[1]))

// ---------------- stage 1: affines + weight images + borders (fused) --------
__global__ void __launch_bounds__(256) prep_stage1(
    const float* __restrict__ w, const float* __restrict__ n,
    const float* __restrict__ A1_w, const float* __restrict__ A1_b,
    const float* __restrict__ B1_w, const float* __restrict__ B1_b,
    const float* __restrict__ A2_w, const float* __restrict__ A2_b,
    const float* __restrict__ B2_w, const float* __restrict__ B2_b,
    const float* __restrict__ conv1_w, const float* __restrict__ conv2_w,
    float* __restrict__ s1, float* __restrict__ n1,
    float* __restrict__ s2, float* __restrict__ n2,
    __half* __restrict__ wH1, __half* __restrict__ wH2,
    __half* __restrict__ p1H, __half* __restrict__ p2H) {
    int blk = blockIdx.x;
    if (blk < 896) {
        int gw = (blk * 256 + threadIdx.x) >> 5, lane = threadIdx.x & 31;
        const float *vec, *Wm, *bias; float* out; int OUT, base;
        if (gw < 2048)      { vec = w; Wm = A1_w; bias = A1_b; out = s1; OUT = 256; base = 0; }
        else if (gw < 4096) { vec = n; Wm = B1_w; bias = B1_b; out = n1; OUT = 256; base = 2048; }
        else if (gw < 6144) { vec = w; Wm = A2_w; bias = A2_b; out = s2; OUT = 256; base = 4096; }
        else                { vec = n; Wm = B2_w; bias = B2_b; out = n2; OUT = 128; base = 6144; }
        int t = gw - base, b = t / OUT, o = t - b * OUT;
        const float* v = vec + b * 512;
        const float* wr = Wm + (size_t)o * 512;
        float s = 0.f;
#pragma unroll 4
        for (int i = lane; i < 512; i += 32) s = fmaf(v[i], wr[i], s);
#pragma unroll
        for (int off = 16; off; off >>= 1) s += __shfl_xor_sync(0xffffffffu, s, off);
        if (lane == 0) out[b * OUT + o] = s + bias[o];
    } else if (blk < 4352) {
        int idx = (blk - 896) * 256 + threadIdx.x;
        int k = idx & 63, nn = (idx >> 6) & 127, s = (idx >> 13) % 36, ob = idx / (36 * 8192);
        int cb = s / 9, tap = s - cb * 9;
        uint32_t off = nn * 64 + (((k >> 3) ^ (nn & 7)) << 3) + (k & 7);
        if (ob < 2) {
            float v = conv1_w[((size_t)(ob * 128 + nn) * 256 + cb * 64 + k) * 9 + tap];
            wH1[((size_t)ob * 36 + s) * 8192 + off] = __float2half_rn(v);
        } else {
            float v = conv2_w[((size_t)nn * 256 + cb * 64 + k) * 9 + tap];
            wH2[(size_t)s * 8192 + off] = __float2half_rn(v);
        }
    } else {
        __half* H; int Hp, p;
        if (blk < 6432) { H = p1H; Hp = 66; p = blk - 4352; }
        else            { H = p2H; Hp = 130; p = blk - 6432; }
        int per = 2 * Hp + 2 * (Hp - 2);
        int b = p / per, r = p % per, c = threadIdx.x;
        int y, x;
        if (r < Hp) { y = 0; x = r; }
        else if (r < 2 * Hp) { y = Hp - 1; x = r - Hp; }
        else { int q = r - 2 * Hp; y = 1 + (q >> 1); x = (q & 1) ? Hp - 1 : 0; }
        H[(((size_t)b * Hp + y) * Hp + x) * 256 + c] = __float2half_rn(0.f);
    }
}

// ---------------- stage 2: demods + pad1 (fused) -----------------------------
__global__ void __launch_bounds__(256) prep_stage2(
    const float* __restrict__ conv1_w, const float* __restrict__ conv2_w,
    const float* __restrict__ x,
    const float* __restrict__ s1, const float* __restrict__ s2,
    float* __restrict__ d1, float* __restrict__ d2,
    __half* __restrict__ p1H) {
    int blk = blockIdx.x, tid = threadIdx.x;
    if (blk < 384) {
        const float* convw; const float* styles; float* demod; int o, COUT;
        if (blk < 256) { convw = conv1_w; styles = s1; demod = d1; o = blk; COUT = 256; }
        else           { convw = conv2_w; styles = s2; demod = d2; o = blk - 256; COUT = 128; }
        float part[8];
#pragma unroll
        for (int b = 0; b < 8; b++) part[b] = 0.f;
        for (int i = tid; i < 256; i += 256) {
            const float* wp = convw + ((size_t)o * 256 + i) * 9;
            float wsq = 0.f;
#pragma unroll
            for (int k = 0; k < 9; k++) { float t = wp[k]; wsq = fmaf(t, t, wsq); }
#pragma unroll
            for (int b = 0; b < 8; b++) {
                float s = styles[b * 256 + i];
                part[b] = fmaf(wsq, s * s, part[b]);
            }
        }
        __shared__ float sm[8][9];
#pragma unroll
        for (int b = 0; b < 8; b++)
#pragma unroll
            for (int off = 16; off; off >>= 1)
                part[b] += __shfl_xor_sync(0xffffffffu, part[b], off);
        int warp = tid >> 5, lane = tid & 31;
        if (lane == 0)
            for (int b = 0; b < 8; b++) sm[warp][b] = part[b];
        __syncthreads();
        if (tid < 8) {
            float t = 0.f;
            for (int w2 = 0; w2 < 8; w2++) t += sm[w2][tid];
            demod[tid * COUT + o] = rsqrtf(t + DEMOD_EPS);
        }
    } else {
        int p = blk - 384;
        int b = p >> 6, y = p & 63, c = tid;
        float sc = s1[b * 256 + c];
        const float* row = x + ((size_t)(b * 256 + c) * 64 + y) * 64;
        size_t dst = (((size_t)b * 66 + y + 1) * 66 + 1) * 256 + c;
        for (int xx = 0; xx < 64; xx++)
            p1H[dst + (size_t)xx * 256] = __float2half_rn(row[xx] * sc);
    }
}

// y1 NHWC fp32 -> upsample2x + style2 -> padded NHWC fp16 (column-sliding)
__global__ void __launch_bounds__(256) prep_pad2(
    const float* __restrict__ y1, const float* __restrict__ s,
    __half* __restrict__ H) {
    int b = blockIdx.y, yy = blockIdx.x, c = threadIdx.x;
    float sc = s[b * 256 + c];
    int ky = yy >> 1, ylo, yhi; float wy;
    if (yy & 1) { ylo = ky; yhi = (ky + 1 < 64) ? ky + 1 : 63; wy = 0.75f; }
    else        { ylo = (ky > 0) ? ky - 1 : 0; yhi = ky;       wy = 0.25f; }
    const float* lo = y1 + (((size_t)b * 64 + ylo) * 64) * 256 + c;
    const float* hi = y1 + (((size_t)b * 64 + yhi) * 64) * 256 + c;
    __half* dst = H + (((size_t)b * 130 + yy + 1) * 130 + 1) * 256 + c;
    float wyc = 1.f - wy;
    float ccur = fmaf(wy, lo[0], wyc * hi[0]);
    float cprev = ccur;
#pragma unroll 4
    for (int kx = 0; kx < 64; kx++) {
        float cnext = (kx + 1 < 64)
            ? fmaf(wy, lo[(kx + 1) * 256], wyc * hi[(kx + 1) * 256]) : ccur;
        dst[(size_t)(2 * kx) * 256]     = __float2half_rn((0.25f * cprev + 0.75f * ccur) * sc);
        dst[(size_t)(2 * kx + 1) * 256] = __float2half_rn((0.75f * ccur + 0.25f * cnext) * sc);
        cprev = ccur; ccur = cnext;
    }
}

// ---------------- mma.sync implicit-GEMM conv (halo-resident A) --------------
// CTA tile: 2 rows x 64 px x 128 oc. 4 warps, 64x64 warp tiles.
// Per channel-block (64 ch), a 4x66-row halo (33KB) is loaded ONCE and all 9
// taps ldmatrix from it with shifted rows. Halo and B double-buffered.
// smem: halo0 [0,33792) halo1 [33792,67584) B0 [67584,83968) B1 [83968,100352)
template <int W, int Hp, int COUT, bool NCHW>
__global__ void __launch_bounds__(128, 2) conv_mma(
    const __half* __restrict__ AH, const __half* __restrict__ BHg,
    const float* __restrict__ demod, const float* __restrict__ noise,
    float* __restrict__ out,
    const float* __restrict__ rgb_in, const float* __restrict__ rgb_w,
    const float* __restrict__ rgb_b, float* __restrict__ rgb_out) {
    extern __shared__ char smem[];
    constexpr uint32_t HALO = 33792;      // 264 rows * 128B
    constexpr uint32_t BOFF = 2 * HALO;   // 67584
    constexpr int TX = W / 64;
    const int tid = threadIdx.x, wid = tid >> 5, lane = tid & 31;
    const int ocb = blockIdx.y, b = blockIdx.z;
    const int bx = blockIdx.x;
    const int y0 = (bx / TX) * 2;
    const int x0 = (bx % TX) * 64;
    const uint32_t sbase = smem_u32(smem);

    const int wm = (wid >> 1) * 64;   // warp pixel offset (0/64)
    const int wn = (wid & 1) * 64;    // warp oc offset   (0/64)

    const int a_csel = lane >> 4;
    const uint32_t b_lane = (((lane >> 4) & 1) << 10) + ((lane & 7) << 7);
    const int b_csel = (lane >> 3) & 1;
    const int swz = lane & 7;

    float c[4][8][4];
#pragma unroll
    for (int i = 0; i < 4; i++)
#pragma unroll
        for (int j = 0; j < 8; j++)
#pragma unroll
            for (int v = 0; v < 4; v++) c[i][j][v] = 0.f;

    const size_t bimg = (size_t)ocb * 36 * 8192;

    // halo: rows r = dyr*66 + gx (dyr 0..3, gx 0..65), 8 x 16B chunks per row
    auto load_halo = [&](int cb, int hbuf) {
        const int ci0 = cb * 64;
        const uint32_t base = sbase + hbuf * HALO;
#pragma unroll
        for (int l = 0; l < 17; l++) {
            int i = tid + l * 128;
            if (i < 2112) {
                int r = i >> 3, q = i & 7;
                int dyr = r / 66, gx = r - dyr * 66;
                size_t src = (((size_t)(b * Hp + y0 + dyr)) * Hp + x0 + gx) * 256 + ci0 + q * 8;
                CPA16CA(base + r * 128 + ((q ^ (r & 7)) << 4), AH + src);
            }
        }
    };
    auto load_B = [&](int s, int bbuf) {
        const char* bh = (const char*)(BHg + bimg + (size_t)s * 8192);
        const uint32_t base = sbase + BOFF + bbuf * 16384;
#pragma unroll
        for (int l = 0; l < 8; l++) {
            int i = tid + l * 128;
            CPA16CG(base + i * 16, bh + i * 16);
        }
    };

    load_halo(0, 0);
    load_B(0, 0);
    CPA_COMMIT();

    for (int s = 0; s < 36; s++) {
        const int bbuf = s & 1;
        const int cb = s / 9, tap = s - cb * 9;
        if (s + 1 < 36) {
            load_B(s + 1, bbuf ^ 1);        // overwrites B(s-1): all warps past MMA(s-1)
            int nx = s + 1;
            if (nx % 9 == 5 && nx / 9 + 1 < 4)
                load_halo(nx / 9 + 1, (nx / 9 + 1) & 1);
            CPA_COMMIT();
            asm volatile("cp.async.wait_group 1;" ::: "memory");
        } else {
            asm volatile("cp.async.wait_group 0;" ::: "memory");
        }
        __syncthreads();

        const int dy = tap / 3 - 1, dx = tap % 3 - 1;
        const uint32_t habase = sbase + (uint32_t)(cb & 1) * HALO;
        uint32_t rhoff[4]; int rhs7[4];
#pragma unroll
        for (int mt = 0; mt < 4; mt++) {
            int P0 = wm + mt * 16;
            int rh = ((P0 >> 6) + dy + 1) * 66 + (P0 & 63) + dx + 1 + (lane & 15);
            rhoff[mt] = habase + (uint32_t)rh * 128;
            rhs7[mt] = rh & 7;
        }
        const uint32_t bw = sbase + BOFF + bbuf * 16384 + wn * 128;
#pragma unroll
        for (int ks = 0; ks < 4; ks++) {
            uint32_t Ah[4][4], Bh[4][4];
            const int kc = ks * 2 + a_csel;
#pragma unroll
            for (int mt = 0; mt < 4; mt++)
                LDSM4(Ah[mt], rhoff[mt] + (uint32_t)((kc ^ rhs7[mt]) << 4));
#pragma unroll
            for (int q = 0; q < 4; q++)
                LDSM4(Bh[q], bw + q * 2048 + b_lane + (((ks * 2 + b_csel) ^ swz) << 4));
#pragma unroll
            for (int mt = 0; mt < 4; mt++)
#pragma unroll
                for (int nt = 0; nt < 8; nt++)
                    MMA16816(c[mt][nt], Ah[mt], (&Bh[nt >> 1][(nt & 1) * 2]));
        }
        __syncthreads();
    }

    // ---- epilogue: stage through smem ---------------------------------------
    float* s_out = (float*)smem;                 // [128 oc][132 px]
    float* sd = s_out + 128 * 132;
    float* sn = sd + 128;
    float* sw = sn + 128;                        // rgb weights [384]
    const int g = lane >> 2, tg = lane & 3;
#pragma unroll
    for (int mt = 0; mt < 4; mt++)
#pragma unroll
        for (int nt = 0; nt < 8; nt++)
#pragma unroll
            for (int v = 0; v < 4; v++) {
                int p = wm + mt * 16 + g + ((v >> 1) << 3);
                int n = wn + nt * 8 + tg * 2 + (v & 1);
                s_out[n * 132 + p] = c[mt][nt][v];
            }
    sd[tid] = demod[b * COUT + ocb * 128 + tid];
    sn[tid] = noise[b * COUT + ocb * 128 + tid];
    if (NCHW)
        for (int i = tid; i < 384; i += 128) sw[i] = rgb_w[i];
    __syncthreads();

    if (NCHW) {
        // conv2: out [b][oc][y][x], tile = 2 rows x 64 px; fused toRGB
        int oc = tid;
        float d = sd[oc], nz = sn[oc];
#pragma unroll
        for (int r = 0; r < 2; r++) {
            float4* dst = (float4*)(out + (((size_t)(b * COUT + oc) * W + y0 + r) * W + x0));
            float4* srow = (float4*)(s_out + oc * 132 + r * 64);
#pragma unroll
            for (int j4 = 0; j4 < 16; j4++) {
                float4 v = srow[j4];
                float r0 = fmaf(v.x, d, nz); r0 = (r0 >= 0.f) ? r0 : NEG_SLOPE * r0;
                float r1 = fmaf(v.y, d, nz); r1 = (r1 >= 0.f) ? r1 : NEG_SLOPE * r1;
                float r2 = fmaf(v.z, d, nz); r2 = (r2 >= 0.f) ? r2 : NEG_SLOPE * r2;
                float r3 = fmaf(v.w, d, nz); r3 = (r3 >= 0.f) ? r3 : NEG_SLOPE * r3;
                float4 rv = make_float4(r0, r1, r2, r3);
                dst[j4] = rv;
                srow[j4] = rv;   // keep activated values for rgb stage
            }
        }
        __syncthreads();
        {
            int xo = x0 + (tid & 63), yo = y0 + (tid >> 6);
            float a0 = 0.f, a1 = 0.f, a2 = 0.f;
#pragma unroll 4
            for (int o = 0; o < 128; o++) {
                float v = s_out[o * 132 + tid];
                a0 = fmaf(v, sw[o], a0);
                a1 = fmaf(v, sw[128 + o], a1);
                a2 = fmaf(v, sw[256 + o], a2);
            }
            float a[3] = {a0, a1, a2};
            int ky = yo >> 1, kx = xo >> 1, ylo, yhi, xlo, xhi;
            float wy, wx;
            if (yo & 1) { ylo = ky; yhi = (ky + 1 < 64) ? ky + 1 : 63; wy = 0.75f; }
            else        { ylo = (ky > 0) ? ky - 1 : 0; yhi = ky;       wy = 0.25f; }
            if (xo & 1) { xlo = kx; xhi = (kx + 1 < 64) ? kx + 1 : 63; wx = 0.75f; }
            else        { xlo = (kx > 0) ? kx - 1 : 0; xhi = kx;       wx = 0.25f; }
#pragma unroll
            for (int ch = 0; ch < 3; ch++) {
                const float* plane = rgb_in + ((size_t)b * 3 + ch) * 4096;
                float v00 = plane[ylo * 64 + xlo], v01 = plane[ylo * 64 + xhi];
                float v10 = plane[yhi * 64 + xlo], v11 = plane[yhi * 64 + xhi];
                float up = wy * (wx * v00 + (1.f - wx) * v01) +
                           (1.f - wy) * (wx * v10 + (1.f - wx) * v11);
                rgb_out[((size_t)(b * 3 + ch) * 128 + yo) * 128 + xo] =
                    (a[ch] + rgb_b[ch] + up) * RES_SCALE;
            }
        }
    } else {
        // conv1: out NHWC [b][y][x][256], tile = 2 rows x 64 px
        int p = tid;
        int y = y0 + (p >> 6), x = p & 63;
        float* dst = out + (((size_t)(b * 64 + y) * 64 + x) * 256) + ocb * 128;
#pragma unroll
        for (int j = 0; j < 128; j += 4) {
            float vv[4];
#pragma unroll
            for (int e = 0; e < 4; e++) {
                int oc = j + e;
                float v = fmaf(s_out[oc * 132 + p], sd[oc], sn[oc]);
                vv[e] = (v >= 0.f) ? v : NEG_SLOPE * v;
            }
            *(float4*)(dst + j) = make_float4(vv[0], vv[1], vv[2], vv[3]);
        }
    }
}

// ---------------- launcher ---------------------------------------------------
extern "C" void kernel_launch(void* const* d_in, const int* in_sizes, int n_in,
                              void* d_out, int out_size) {
    const float* x       = (const float*)d_in[0];
    const float* w       = (const float*)d_in[1];
    const float* n       = (const float*)d_in[2];
    const float* rgb     = (const float*)d_in[3];
    const float* conv1_w = (const float*)d_in[4];
    const float* A1_w    = (const float*)d_in[5];
    const float* A1_b    = (const float*)d_in[6];
    const float* B1_w    = (const float*)d_in[7];
    const float* B1_b    = (const float*)d_in[8];
    const float* conv2_w = (const float*)d_in[9];
    const float* A2_w    = (const float*)d_in[10];
    const float* A2_b    = (const float*)d_in[11];
    const float* B2_w    = (const float*)d_in[12];
    const float* B2_b    = (const float*)d_in[13];
    const float* rgb_w   = (const float*)d_in[14];
    const float* rgb_b   = (const float*)d_in[15];

    static float* p_y1 = nullptr;
    static __half *p1H, *p2H, *wH1, *wH2;
    static float *p_s1, *p_n1, *p_s2, *p_n2, *p_d1, *p_d2;
    if (!p_y1) {
        cudaGetSymbolAddress((void**)&p_y1, g_y1);
        cudaGetSymbolAddress((void**)&p1H, g_p1H);
        cudaGetSymbolAddress((void**)&p2H, g_p2H);
        cudaGetSymbolAddress((void**)&wH1, g_wH1);
        cudaGetSymbolAddress((void**)&wH2, g_wH2);
        cudaGetSymbolAddress((void**)&p_s1, g_s1);
        cudaGetSymbolAddress((void**)&p_n1, g_n1);
        cudaGetSymbolAddress((void**)&p_s2, g_s2);
        cudaGetSymbolAddress((void**)&p_n2, g_n2);
        cudaGetSymbolAddress((void**)&p_d1, g_d1);
        cudaGetSymbolAddress((void**)&p_d2, g_d2);
        cudaFuncSetAttribute(conv_mma<64, 66, 256, false>,
                             cudaFuncAttributeMaxDynamicSharedMemorySize, 100352);
        cudaFuncSetAttribute(conv_mma<128, 130, 128, true>,
                             cudaFuncAttributeMaxDynamicSharedMemorySize, 100352);
    }

    float* xout = (float*)d_out;                         // [8,128,128,128]
    float* rgbout = xout + (size_t)8 * 128 * 128 * 128;  // [8,3,128,128]

    prep_stage1<<<10560, 256>>>(w, n, A1_w, A1_b, B1_w, B1_b, A2_w, A2_b,
                                B2_w, B2_b, conv1_w, conv2_w,
                                p_s1, p_n1, p_s2, p_n2, wH1, wH2, p1H, p2H);
    prep_stage2<<<896, 256>>>(conv1_w, conv2_w, x, p_s1, p_s2, p_d1, p_d2, p1H);

    conv_mma<64, 66, 256, false><<<dim3(32, 2, 8), 128, 100352>>>(
        p1H, wH1, p_d1, p_n1, p_y1, nullptr, nullptr, nullptr, nullptr);

    prep_pad2<<<dim3(128, 8), 256>>>(p_y1, p_s2, p2H);

    conv_mma<128, 130, 128, true><<<dim3(128, 1, 8), 128, 100352>>>(
        p2H, wH2, p_d2, p_n2, xout, rgb, rgb_w, rgb_b, rgbout);
}